// round 3
// baseline (speedup 1.0000x reference)
#include <cuda_runtime.h>
#include <cuda_bf16.h>
#include <cstdint>

// Problem dims
#define BB 4
#define SS 2048
#define DD 1024
#define EE 2048
#define NN 16
#define KK 4
#define MM (BB*SS)          // 8192 tokens

// ---------------- scratch (device globals; no allocation allowed) ----------
__device__ __align__(256) __nv_bfloat16 g_xln[MM*DD];        // 16.8MB
__device__ __align__(256) __nv_bfloat16 g_xpg[(size_t)MM*2*EE]; // x_proj (xp|gate) 67MB
__device__ __align__(256) __nv_bfloat16 g_xc [(size_t)MM*EE];   // conv+silu out
__device__ __align__(256) __nv_bfloat16 g_uv [(size_t)MM*2*EE]; // (U+bc | V+bd)
__device__ __align__(256) __nv_bfloat16 g_xg [(size_t)MM*EE];   // gated ssm out
__device__ __align__(256) __nv_bfloat16 g_win [(size_t)2*EE*DD];
__device__ __align__(256) __nv_bfloat16 g_wcd [(size_t)2*EE*EE];
__device__ __align__(256) __nv_bfloat16 g_wout[(size_t)DD*EE];
__device__ float g_a[EE];
__device__ float g_cc[EE];
__device__ float g_biascat[2*EE];
__device__ float g_ylast[MM*8];   // [b*E+e][chunk]  (MM used loosely: B*E=8192)
__device__ float g_yinit[MM*8];

// ---------------- helpers ----------------
__device__ __forceinline__ uint32_t smem_u32(const void* p){
    return (uint32_t)__cvta_generic_to_shared(p);
}
__device__ __forceinline__ void cp_async16(uint32_t saddr, const void* gptr){
    asm volatile("cp.async.cg.shared.global [%0], [%1], 16;" :: "r"(saddr), "l"(gptr));
}
__device__ __forceinline__ void cp_commit(){ asm volatile("cp.async.commit_group;"); }
__device__ __forceinline__ void ldsm4(uint32_t& r0,uint32_t& r1,uint32_t& r2,uint32_t& r3,uint32_t addr){
    asm volatile("ldmatrix.sync.aligned.m8n8.x4.shared.b16 {%0,%1,%2,%3}, [%4];"
        : "=r"(r0),"=r"(r1),"=r"(r2),"=r"(r3) : "r"(addr));
}
__device__ __forceinline__ void mma16816(float* c, uint32_t a0,uint32_t a1,uint32_t a2,uint32_t a3,
                                         uint32_t b0,uint32_t b1){
    asm volatile("mma.sync.aligned.m16n8k16.row.col.f32.bf16.bf16.f32 "
        "{%0,%1,%2,%3},{%4,%5,%6,%7},{%8,%9},{%0,%1,%2,%3};"
        : "+f"(c[0]),"+f"(c[1]),"+f"(c[2]),"+f"(c[3])
        : "r"(a0),"r"(a1),"r"(a2),"r"(a3),"r"(b0),"r"(b1));
}
__device__ __forceinline__ float sigf(float x){ return 1.f/(1.f+__expf(-x)); }

// ---------------- precompute: weight bf16 conversion ----------------
__global__ void wconv_kernel(const float* __restrict__ win, const float* __restrict__ wc,
                             const float* __restrict__ wd, const float* __restrict__ wout){
    size_t i = (size_t)blockIdx.x*blockDim.x + threadIdx.x;  // 4194304 threads
    // W_in: 2E x D = 4096*1024 = 4194304
    g_win[i] = __float2bfloat16(win[i]);
    // W_c / W_d: 2048*2048 = 4194304 each -> concatenated
    g_wcd[i]              = __float2bfloat16(wc[i]);
    g_wcd[(size_t)4194304 + i] = __float2bfloat16(wd[i]);
    // W_out: 1024*2048 = 2097152
    if (i < (size_t)DD*EE) g_wout[i] = __float2bfloat16(wout[i]);
}

// ---------------- precompute: a_e, c_e, bias_cat ----------------
__global__ void pre_small(const float* __restrict__ log_delta, const float* __restrict__ Amat,
                          const float* __restrict__ Bmat, const float* __restrict__ bc,
                          const float* __restrict__ bd){
    int e = blockIdx.x*blockDim.x + threadIdx.x;
    if (e < EE){
        float dl = log_delta[e];
        float sp = (dl > 20.f) ? dl : log1pf(expf(dl));
        g_a[e] = expf(-sp);
        float s = 0.f;
        #pragma unroll
        for (int n=0; n<NN; n++) s += Amat[e*NN+n]*Bmat[e*NN+n];
        g_cc[e] = s;
        g_biascat[e]    = bc[e];
        g_biascat[EE+e] = bd[e];
    }
}

// ---------------- layernorm -> bf16 ----------------
__global__ void ln_kernel(const float* __restrict__ x, const float* __restrict__ g,
                          const float* __restrict__ bta){
    int m = blockIdx.x;
    int tid = threadIdx.x;
    const float* row = x + (size_t)m*DD;
    float v[4], s=0.f, s2=0.f;
    #pragma unroll
    for (int i=0;i<4;i++){ v[i]=row[tid+i*256]; s+=v[i]; s2+=v[i]*v[i]; }
    #pragma unroll
    for (int o=16;o;o>>=1){ s += __shfl_xor_sync(~0u,s,o); s2 += __shfl_xor_sync(~0u,s2,o); }
    __shared__ float sh[2][8];
    int w = tid>>5, l = tid&31;
    if (l==0){ sh[0][w]=s; sh[1][w]=s2; }
    __syncthreads();
    s=0.f; s2=0.f;
    #pragma unroll
    for (int j=0;j<8;j++){ s+=sh[0][j]; s2+=sh[1][j]; }
    float mu = s*(1.f/DD);
    float var = s2*(1.f/DD) - mu*mu;
    float rs = rsqrtf(var + 1e-5f);
    #pragma unroll
    for (int i=0;i<4;i++){
        int c = tid+i*256;
        g_xln[(size_t)m*DD + c] = __float2bfloat16((v[i]-mu)*rs*g[c] + bta[c]);
    }
}

// ---------------- GEMM: C[m,n] = sum_k A[m,k]*B[n,k] (+bias)(+resid) -------
// MODE 0: A=g_xln(K=1024) B=g_win  N=4096 -> g_xpg bf16, bias=param
// MODE 1: A=g_xc (K=2048) B=g_wcd  N=4096 -> g_uv  bf16, bias=g_biascat
// MODE 2: A=g_xg (K=2048) B=g_wout N=1024 -> fp32 out,   bias=param, +resid
template<int MODE>
__global__ __launch_bounds__(256,2) void gemm_kernel(const float* __restrict__ bias_p,
                                                     const float* __restrict__ resid,
                                                     float* __restrict__ outf){
    constexpr int N_ = (MODE==2)?1024:4096;
    constexpr int K_ = (MODE==0)?1024:2048;
    constexpr int KT = K_/32;
    const __nv_bfloat16* A  = (MODE==0)? g_xln : (MODE==1)? g_xc : g_xg;
    const __nv_bfloat16* Bw = (MODE==0)? g_win : (MODE==1)? g_wcd : g_wout;
    __nv_bfloat16* Cb = (MODE==0)? g_xpg : g_uv;
    const float* bias = (MODE==1)? g_biascat : bias_p;

    __shared__ __nv_bfloat16 As[2][128*40];
    __shared__ __nv_bfloat16 Bs[2][128*40];
    constexpr uint32_t BUFB = 128*40*2;

    const int tid = threadIdx.x;
    const int lane = tid & 31, warp = tid >> 5;
    const int wm = warp >> 1, wn = warp & 1;        // 4 x 2 warp grid
    const int bm = blockIdx.y * 128, bn = blockIdx.x * 128;

    const uint32_t sA = smem_u32(&As[0][0]);
    const uint32_t sB = smem_u32(&Bs[0][0]);

    float acc[2][8][4];
    #pragma unroll
    for (int i=0;i<2;i++) for (int j=0;j<8;j++) for (int q=0;q<4;q++) acc[i][j][q]=0.f;

    // global->smem tile loader (2 chunks of A + 2 of B per thread)
    auto load_tile = [&](int kt, int buf){
        #pragma unroll
        for (int h=0; h<2; h++){
            int c = tid + h*256;
            int row = c >> 2, kc = (c & 3) * 8;
            const __nv_bfloat16* ga = A  + (size_t)(bm+row)*K_ + kt*32 + kc;
            const __nv_bfloat16* gb = Bw + (size_t)(bn+row)*K_ + kt*32 + kc;
            uint32_t so = (uint32_t)((row*40 + kc)*2) + (uint32_t)buf*BUFB;
            cp_async16(sA + so, ga);
            cp_async16(sB + so, gb);
        }
        cp_commit();
    };

    const int la_row = lane & 15;
    const int la_c8  = (lane >> 4) << 3;
    const int lb_row = ((lane >> 4) << 3) + (lane & 7);
    const int lb_c8  = ((lane >> 3) & 1) << 3;

    load_tile(0, 0);
    int buf = 0;
    for (int kt=0; kt<KT; kt++){
        if (kt+1 < KT) load_tile(kt+1, buf^1);
        if (kt+1 < KT) { asm volatile("cp.async.wait_group 1;"); }
        else           { asm volatile("cp.async.wait_group 0;"); }
        __syncthreads();

        uint32_t baseA = sA + (uint32_t)buf*BUFB;
        uint32_t baseB = sB + (uint32_t)buf*BUFB;
        uint32_t a[2][4], bfr[4][4];
        #pragma unroll
        for (int k16=0;k16<2;k16++){
            int kb = k16*16;
            #pragma unroll
            for (int i=0;i<2;i++){
                uint32_t ad = baseA + (uint32_t)(((wm*32 + i*16 + la_row)*40 + kb + la_c8)*2);
                ldsm4(a[i][0],a[i][1],a[i][2],a[i][3], ad);
            }
            #pragma unroll
            for (int jp=0;jp<4;jp++){
                uint32_t bd = baseB + (uint32_t)(((wn*64 + jp*16 + lb_row)*40 + kb + lb_c8)*2);
                ldsm4(bfr[jp][0],bfr[jp][1],bfr[jp][2],bfr[jp][3], bd);
            }
            #pragma unroll
            for (int i=0;i<2;i++){
                #pragma unroll
                for (int j=0;j<8;j++){
                    int jp=j>>1, o=(j&1)*2;
                    mma16816(acc[i][j], a[i][0],a[i][1],a[i][2],a[i][3], bfr[jp][o], bfr[jp][o+1]);
                }
            }
        }
        __syncthreads();
        buf ^= 1;
    }

    // epilogue
    const int ro = lane >> 2, co = (lane & 3) * 2;
    #pragma unroll
    for (int i=0;i<2;i++){
        #pragma unroll
        for (int j=0;j<8;j++){
            int r  = bm + wm*32 + i*16 + ro;
            int cc = bn + wn*64 + j*8 + co;
            float b0 = bias[cc], b1 = bias[cc+1];
            float v0 = acc[i][j][0]+b0, v1 = acc[i][j][1]+b1;
            float v2 = acc[i][j][2]+b0, v3 = acc[i][j][3]+b1;
            if (MODE==2){
                size_t o0 = (size_t)r*N_ + cc;
                size_t o1 = (size_t)(r+8)*N_ + cc;
                outf[o0]   = v0 + resid[o0];
                outf[o0+1] = v1 + resid[o0+1];
                outf[o1]   = v2 + resid[o1];
                outf[o1+1] = v3 + resid[o1+1];
            } else {
                *reinterpret_cast<__nv_bfloat162*>(&Cb[(size_t)r*N_ + cc])
                    = __floats2bfloat162_rn(v0, v1);
                *reinterpret_cast<__nv_bfloat162*>(&Cb[(size_t)(r+8)*N_ + cc])
                    = __floats2bfloat162_rn(v2, v3);
            }
        }
    }
}

// ---------------- causal depthwise conv K=4 + silu ----------------
// thread handles 2 channels (e,e+1) over a 128-long s chunk
__global__ void conv_kernel(const float* __restrict__ cw, const float* __restrict__ cb){
    int id = blockIdx.x*blockDim.x + threadIdx.x;     // 65536
    int ep = id & 1023;
    int c  = (id >> 10) & 15;
    int b  = id >> 14;
    int e  = ep*2;
    float w[4][2];
    #pragma unroll
    for (int k=0;k<4;k++){ w[k][0]=cw[e*4+k]; w[k][1]=cw[(e+1)*4+k]; }
    float bi0 = cb[e], bi1 = cb[e+1];
    const __nv_bfloat162* XP = reinterpret_cast<const __nv_bfloat162*>(g_xpg);
    __nv_bfloat162* XC = reinterpret_cast<__nv_bfloat162*>(g_xc);
    int s0 = c*128;
    float2 win[3];
    #pragma unroll
    for (int k=0;k<3;k++){
        int s = s0 - 3 + k;
        if (s >= 0){
            __nv_bfloat162 t = XP[((size_t)(b*SS+s)*(2*EE) + e) >> 1];
            win[k] = make_float2(__low2float(t), __high2float(t));
        } else win[k] = make_float2(0.f, 0.f);
    }
    for (int s=s0; s<s0+128; s++){
        __nv_bfloat162 t = XP[((size_t)(b*SS+s)*(2*EE) + e) >> 1];
        float2 cur = make_float2(__low2float(t), __high2float(t));
        float ax = bi0 + w[0][0]*win[0].x + w[1][0]*win[1].x + w[2][0]*win[2].x + w[3][0]*cur.x;
        float ay = bi1 + w[0][1]*win[0].y + w[1][1]*win[1].y + w[2][1]*win[2].y + w[3][1]*cur.y;
        ax = ax * sigf(ax);
        ay = ay * sigf(ay);
        XC[((size_t)(b*SS+s)*EE + e) >> 1] = __floats2bfloat162_rn(ax, ay);
        win[0]=win[1]; win[1]=win[2]; win[2]=cur;
    }
}

// ---------------- chunked linear scan ----------------
// y_t = a*y_{t-1} + c*u_t,  u_t = U*sigmoid(V);  8 chunks of 256 per (b,e)
__global__ void scanA_kernel(){
    int id = blockIdx.x*blockDim.x + threadIdx.x;   // 65536
    int e = id & 2047, c = (id >> 11) & 7, b = id >> 14;
    float a = g_a[e], cc = g_cc[e];
    float y = 0.f;
    size_t base = ((size_t)b*SS + c*256) * (2*EE);
    #pragma unroll 4
    for (int t=0;t<256;t++){
        size_t o = base + (size_t)t*(2*EE);
        float U = __bfloat162float(g_uv[o + e]);
        float V = __bfloat162float(g_uv[o + EE + e]);
        y = a*y + cc*(U * sigf(V));
    }
    g_ylast[((b<<11)+e)*8 + c] = y;
}
__global__ void scanB_kernel(){
    int id = blockIdx.x*blockDim.x + threadIdx.x;   // 8192 = b*2048+e
    int e = id & 2047;
    float a = g_a[e];
    float aL = a;
    #pragma unroll
    for (int i=0;i<8;i++) aL *= aL;  // a^256
    float y = 0.f;
    #pragma unroll
    for (int c=0;c<8;c++){
        g_yinit[id*8 + c] = y;
        y = g_ylast[id*8 + c] + aL*y;
    }
}
__global__ void scanC_kernel(){
    int id = blockIdx.x*blockDim.x + threadIdx.x;   // 65536
    int e = id & 2047, c = (id >> 11) & 7, b = id >> 14;
    float a = g_a[e], cc = g_cc[e];
    float y = g_yinit[((b<<11)+e)*8 + c];
    size_t base = ((size_t)b*SS + c*256) * (2*EE);
    size_t obase = ((size_t)b*SS + c*256) * EE;
    #pragma unroll 4
    for (int t=0;t<256;t++){
        size_t o = base + (size_t)t*(2*EE);
        float U = __bfloat162float(g_uv[o + e]);
        float V = __bfloat162float(g_uv[o + EE + e]);
        y = a*y + cc*(U * sigf(V));
        float gt = __bfloat162float(g_xpg[o + EE + e]);   // gate
        g_xg[obase + (size_t)t*EE + e] = __float2bfloat16(y * sigf(gt));
    }
}

// ---------------- launch ----------------
extern "C" void kernel_launch(void* const* d_in, const int* in_sizes, int n_in,
                              void* d_out, int out_size){
    const float* x         = (const float*)d_in[0];
    const float* ln_g      = (const float*)d_in[1];
    const float* ln_b      = (const float*)d_in[2];
    const float* W_in      = (const float*)d_in[3];
    const float* b_in      = (const float*)d_in[4];
    const float* conv_w    = (const float*)d_in[5];
    const float* conv_b    = (const float*)d_in[6];
    const float* Amat      = (const float*)d_in[7];
    const float* Bmat      = (const float*)d_in[8];
    const float* W_c       = (const float*)d_in[9];
    const float* b_c       = (const float*)d_in[10];
    const float* W_d       = (const float*)d_in[11];
    const float* b_d       = (const float*)d_in[12];
    const float* log_delta = (const float*)d_in[13];
    const float* W_out     = (const float*)d_in[14];
    const float* b_out     = (const float*)d_in[15];
    float* out = (float*)d_out;

    wconv_kernel<<<16384, 256>>>(W_in, W_c, W_d, W_out);
    pre_small<<<8, 256>>>(log_delta, Amat, Bmat, b_c, b_d);
    ln_kernel<<<MM, 256>>>(x, ln_g, ln_b);
    gemm_kernel<0><<<dim3(32,64), 256>>>(b_in, nullptr, nullptr);
    conv_kernel<<<256, 256>>>(conv_w, conv_b);
    gemm_kernel<1><<<dim3(32,64), 256>>>(nullptr, nullptr, nullptr);
    scanA_kernel<<<256, 256>>>();
    scanB_kernel<<<32, 256>>>();
    scanC_kernel<<<256, 256>>>();
    gemm_kernel<2><<<dim3(8,64), 256>>>(b_out, x, out);
}

// round 10
// speedup vs baseline: 1.2075x; 1.2075x over previous
#include <cuda_runtime.h>
#include <cuda_bf16.h>
#include <cstdint>

// Problem dims
#define BB 4
#define SS 2048
#define DD 1024
#define EE 2048
#define NN 16
#define MM (BB*SS)          // 8192 tokens
#define CH 16               // scan chunks per sequence

// ---------------- scratch (device globals; no allocation allowed) ----------
__device__ __align__(256) __nv_bfloat16 g_xln[MM*DD];
__device__ __align__(256) __nv_bfloat16 g_xpg[(size_t)MM*2*EE]; // x_proj (xp|gate)
__device__ __align__(256) __nv_bfloat16 g_xc [(size_t)MM*EE];   // conv+silu out; later reused for cc*u
__device__ __align__(256) __nv_bfloat16 g_uv [(size_t)MM*2*EE]; // (U+bc | V+bd)
__device__ __align__(256) __nv_bfloat16 g_xg [(size_t)MM*EE];   // gated ssm out
__device__ __align__(256) __nv_bfloat16 g_win [(size_t)2*EE*DD];
__device__ __align__(256) __nv_bfloat16 g_wcd [(size_t)2*EE*EE];
__device__ __align__(256) __nv_bfloat16 g_wout[(size_t)DD*EE];
__device__ float g_a[EE];
__device__ float g_cc[EE];
__device__ float g_biascat[2*EE];
__device__ float g_ylast[BB*EE*CH];
__device__ float g_yinit[BB*EE*CH];

// ---------------- helpers ----------------
__device__ __forceinline__ uint32_t smem_u32(const void* p){
    return (uint32_t)__cvta_generic_to_shared(p);
}
__device__ __forceinline__ void cp_async16(uint32_t saddr, const void* gptr){
    asm volatile("cp.async.cg.shared.global [%0], [%1], 16;" :: "r"(saddr), "l"(gptr));
}
__device__ __forceinline__ void cp_commit(){ asm volatile("cp.async.commit_group;"); }
__device__ __forceinline__ void ldsm4(uint32_t& r0,uint32_t& r1,uint32_t& r2,uint32_t& r3,uint32_t addr){
    asm volatile("ldmatrix.sync.aligned.m8n8.x4.shared.b16 {%0,%1,%2,%3}, [%4];"
        : "=r"(r0),"=r"(r1),"=r"(r2),"=r"(r3) : "r"(addr));
}
__device__ __forceinline__ void mma16816(float* c, uint32_t a0,uint32_t a1,uint32_t a2,uint32_t a3,
                                         uint32_t b0,uint32_t b1){
    asm volatile("mma.sync.aligned.m16n8k16.row.col.f32.bf16.bf16.f32 "
        "{%0,%1,%2,%3},{%4,%5,%6,%7},{%8,%9},{%0,%1,%2,%3};"
        : "+f"(c[0]),"+f"(c[1]),"+f"(c[2]),"+f"(c[3])
        : "r"(a0),"r"(a1),"r"(a2),"r"(a3),"r"(b0),"r"(b1));
}
__device__ __forceinline__ float sigf(float x){ return 1.f/(1.f+__expf(-x)); }
__device__ __forceinline__ uint32_t bf2u(__nv_bfloat162 v){
    uint32_t u;
    memcpy(&u, &v, 4);
    return u;
}

// ---------------- precompute: weight bf16 conversion (vectorized) ----------
__global__ void wconv_kernel(const float* __restrict__ win, const float* __restrict__ wc,
                             const float* __restrict__ wd, const float* __restrict__ wout){
    size_t idx = (size_t)blockIdx.x*blockDim.x + threadIdx.x;  // 1048576 threads
    size_t i4 = idx*4;
    auto cv = [](float4 v)->uint2{
        uint2 r;
        r.x = bf2u(__floats2bfloat162_rn(v.x, v.y));
        r.y = bf2u(__floats2bfloat162_rn(v.z, v.w));
        return r;
    };
    // W_in: 4194304 elems
    *reinterpret_cast<uint2*>(&g_win[i4]) = cv(*reinterpret_cast<const float4*>(&win[i4]));
    // W_c / W_d concatenated
    *reinterpret_cast<uint2*>(&g_wcd[i4]) = cv(*reinterpret_cast<const float4*>(&wc[i4]));
    *reinterpret_cast<uint2*>(&g_wcd[(size_t)4194304 + i4]) = cv(*reinterpret_cast<const float4*>(&wd[i4]));
    // W_out: 2097152 elems
    if (i4 < (size_t)DD*EE)
        *reinterpret_cast<uint2*>(&g_wout[i4]) = cv(*reinterpret_cast<const float4*>(&wout[i4]));
}

// ---------------- precompute: a_e, c_e, bias_cat ----------------
__global__ void pre_small(const float* __restrict__ log_delta, const float* __restrict__ Amat,
                          const float* __restrict__ Bmat, const float* __restrict__ bc,
                          const float* __restrict__ bd){
    int e = blockIdx.x*blockDim.x + threadIdx.x;
    if (e < EE){
        float dl = log_delta[e];
        float sp = (dl > 20.f) ? dl : log1pf(expf(dl));
        g_a[e] = expf(-sp);
        float s = 0.f;
        #pragma unroll
        for (int n=0; n<NN; n++) s += Amat[e*NN+n]*Bmat[e*NN+n];
        g_cc[e] = s;
        g_biascat[e]    = bc[e];
        g_biascat[EE+e] = bd[e];
    }
}

// ---------------- layernorm -> bf16 ----------------
__global__ void ln_kernel(const float* __restrict__ x, const float* __restrict__ g,
                          const float* __restrict__ bta){
    int m = blockIdx.x;
    int tid = threadIdx.x;
    const float* row = x + (size_t)m*DD;
    float v[4], s=0.f, s2=0.f;
    #pragma unroll
    for (int i=0;i<4;i++){ v[i]=row[tid+i*256]; s+=v[i]; s2+=v[i]*v[i]; }
    #pragma unroll
    for (int o=16;o;o>>=1){ s += __shfl_xor_sync(~0u,s,o); s2 += __shfl_xor_sync(~0u,s2,o); }
    __shared__ float sh[2][8];
    int w = tid>>5, l = tid&31;
    if (l==0){ sh[0][w]=s; sh[1][w]=s2; }
    __syncthreads();
    s=0.f; s2=0.f;
    #pragma unroll
    for (int j=0;j<8;j++){ s+=sh[0][j]; s2+=sh[1][j]; }
    float mu = s*(1.f/DD);
    float var = s2*(1.f/DD) - mu*mu;
    float rs = rsqrtf(var + 1e-5f);
    #pragma unroll
    for (int i=0;i<4;i++){
        int c = tid+i*256;
        g_xln[(size_t)m*DD + c] = __float2bfloat16((v[i]-mu)*rs*g[c] + bta[c]);
    }
}

// ---------------- GEMM: C[m,n] = sum_k A[m,k]*B[n,k] (+bias)(+resid) -------
// mma.sync, 128x128 block tile, 32-wide K chunks, 4-stage cp.async pipeline,
// ONE __syncthreads per K chunk.
// MODE 0: A=g_xln(K=1024) B=g_win  -> g_xpg bf16, bias=param
// MODE 1: A=g_xc (K=2048) B=g_wcd  -> g_uv  bf16, bias=g_biascat
// MODE 2: A=g_xg (K=2048) B=g_wout -> fp32 out, bias=param, +resid
#define STAGE_B 10240u                 // 128*40*2 bytes per tensor per stage
#define GEMM_SMEM (8*10240)            // 4 stages x (A+B) = 80KB

template<int MODE>
__global__ __launch_bounds__(256,2) void gemm_kernel(const float* __restrict__ bias_p,
                                                     const float* __restrict__ resid,
                                                     float* __restrict__ outf){
    constexpr int N_ = (MODE==2)?1024:4096;
    constexpr int K_ = (MODE==0)?1024:2048;
    constexpr int KT = K_/32;
    const __nv_bfloat16* A  = (MODE==0)? g_xln : (MODE==1)? g_xc : g_xg;
    const __nv_bfloat16* Bw = (MODE==0)? g_win : (MODE==1)? g_wcd : g_wout;
    __nv_bfloat16* Cb = (MODE==0)? g_xpg : g_uv;
    const float* bias = (MODE==1)? g_biascat : bias_p;

    extern __shared__ __nv_bfloat16 smem[];
    const uint32_t sA = smem_u32(smem);            // A stages: [0, 4*STAGE_B)
    const uint32_t sB = sA + 4*STAGE_B;            // B stages: [4*STAGE_B, 8*STAGE_B)

    const int tid = threadIdx.x;
    const int lane = tid & 31, warp = tid >> 5;
    const int wm = warp >> 1, wn = warp & 1;        // 4 x 2 warp grid
    const int bm = blockIdx.y * 128, bn = blockIdx.x * 128;

    float acc[2][8][4];
    #pragma unroll
    for (int i=0;i<2;i++) for (int j=0;j<8;j++) for (int q=0;q<4;q++) acc[i][j][q]=0.f;

    auto load_tile = [&](int kt, int s){
        #pragma unroll
        for (int h=0; h<2; h++){
            int c = tid + h*256;
            int row = c >> 2, kc = (c & 3) * 8;
            const __nv_bfloat16* ga = A  + (size_t)(bm+row)*K_ + kt*32 + kc;
            const __nv_bfloat16* gb = Bw + (size_t)(bn+row)*K_ + kt*32 + kc;
            uint32_t so = (uint32_t)((row*40 + kc)*2) + (uint32_t)s*STAGE_B;
            cp_async16(sA + so, ga);
            cp_async16(sB + so, gb);
        }
        cp_commit();
    };

    const int la_row = lane & 15;
    const int la_c8  = (lane >> 4) << 3;
    const int lb_row = ((lane >> 4) << 3) + (lane & 7);
    const int lb_c8  = ((lane >> 3) & 1) << 3;

    // prologue: fill 3 of 4 stages
    load_tile(0,0); load_tile(1,1); load_tile(2,2);

    for (int kt=0; kt<KT; kt++){
        int rem = KT-1-kt;
        if (rem >= 2)      { asm volatile("cp.async.wait_group 2;" ::: "memory"); }
        else if (rem == 1) { asm volatile("cp.async.wait_group 1;" ::: "memory"); }
        else               { asm volatile("cp.async.wait_group 0;" ::: "memory"); }
        __syncthreads();
        if (kt+3 < KT) load_tile(kt+3, (kt+3)&3);

        uint32_t baseA = sA + (uint32_t)(kt&3)*STAGE_B;
        uint32_t baseB = sB + (uint32_t)(kt&3)*STAGE_B;
        uint32_t a[2][4], bfr[4][4];
        #pragma unroll
        for (int k16=0;k16<2;k16++){
            int kb = k16*16;
            #pragma unroll
            for (int i=0;i<2;i++){
                uint32_t ad = baseA + (uint32_t)(((wm*32 + i*16 + la_row)*40 + kb + la_c8)*2);
                ldsm4(a[i][0],a[i][1],a[i][2],a[i][3], ad);
            }
            #pragma unroll
            for (int jp=0;jp<4;jp++){
                uint32_t bd = baseB + (uint32_t)(((wn*64 + jp*16 + lb_row)*40 + kb + lb_c8)*2);
                ldsm4(bfr[jp][0],bfr[jp][1],bfr[jp][2],bfr[jp][3], bd);
            }
            #pragma unroll
            for (int i=0;i<2;i++){
                #pragma unroll
                for (int j=0;j<8;j++){
                    int jp=j>>1, o=(j&1)*2;
                    mma16816(acc[i][j], a[i][0],a[i][1],a[i][2],a[i][3], bfr[jp][o], bfr[jp][o+1]);
                }
            }
        }
    }

    // epilogue
    const int ro = lane >> 2, co = (lane & 3) * 2;
    #pragma unroll
    for (int i=0;i<2;i++){
        #pragma unroll
        for (int j=0;j<8;j++){
            int r  = bm + wm*32 + i*16 + ro;
            int cc = bn + wn*64 + j*8 + co;
            float b0 = bias[cc], b1 = bias[cc+1];
            float v0 = acc[i][j][0]+b0, v1 = acc[i][j][1]+b1;
            float v2 = acc[i][j][2]+b0, v3 = acc[i][j][3]+b1;
            if (MODE==2){
                size_t o0 = (size_t)r*N_ + cc;
                size_t o1 = (size_t)(r+8)*N_ + cc;
                outf[o0]   = v0 + resid[o0];
                outf[o0+1] = v1 + resid[o0+1];
                outf[o1]   = v2 + resid[o1];
                outf[o1+1] = v3 + resid[o1+1];
            } else {
                *reinterpret_cast<__nv_bfloat162*>(&Cb[(size_t)r*N_ + cc])
                    = __floats2bfloat162_rn(v0, v1);
                *reinterpret_cast<__nv_bfloat162*>(&Cb[(size_t)(r+8)*N_ + cc])
                    = __floats2bfloat162_rn(v2, v3);
            }
        }
    }
}

// ---------------- causal depthwise conv K=4 + silu ----------------
__global__ void conv_kernel(const float* __restrict__ cw, const float* __restrict__ cb){
    int id = blockIdx.x*blockDim.x + threadIdx.x;     // 65536
    int ep = id & 1023;
    int c  = (id >> 10) & 15;
    int b  = id >> 14;
    int e  = ep*2;
    float w[4][2];
    #pragma unroll
    for (int k=0;k<4;k++){ w[k][0]=cw[e*4+k]; w[k][1]=cw[(e+1)*4+k]; }
    float bi0 = cb[e], bi1 = cb[e+1];
    const __nv_bfloat162* XP = reinterpret_cast<const __nv_bfloat162*>(g_xpg);
    __nv_bfloat162* XC = reinterpret_cast<__nv_bfloat162*>(g_xc);
    int s0 = c*128;
    float2 win[3];
    #pragma unroll
    for (int k=0;k<3;k++){
        int s = s0 - 3 + k;
        if (s >= 0){
            __nv_bfloat162 t = XP[((size_t)(b*SS+s)*(2*EE) + e) >> 1];
            win[k] = make_float2(__low2float(t), __high2float(t));
        } else win[k] = make_float2(0.f, 0.f);
    }
    #pragma unroll 4
    for (int s=s0; s<s0+128; s++){
        __nv_bfloat162 t = XP[((size_t)(b*SS+s)*(2*EE) + e) >> 1];
        float2 cur = make_float2(__low2float(t), __high2float(t));
        float ax = bi0 + w[0][0]*win[0].x + w[1][0]*win[1].x + w[2][0]*win[2].x + w[3][0]*cur.x;
        float ay = bi1 + w[0][1]*win[0].y + w[1][1]*win[1].y + w[2][1]*win[2].y + w[3][1]*cur.y;
        ax = ax * sigf(ax);
        ay = ay * sigf(ay);
        XC[((size_t)(b*SS+s)*EE + e) >> 1] = __floats2bfloat162_rn(ax, ay);
        win[0]=win[1]; win[1]=win[2]; win[2]=cur;
    }
}

// ---------------- chunked linear scan (pair-vectorized, 16 chunks of 128) --
// y_t = a*y_{t-1} + cu_t,  cu_t = cc*U*sigmoid(V). scanA stores cu into g_xc.
#define CLEN (SS/CH)   // 128
__global__ void scanA_kernel(){
    int id = blockIdx.x*blockDim.x + threadIdx.x;   // 65536
    int ep = id & 1023, c = (id >> 10) & (CH-1), b = id >> 14;
    int e = ep*2;
    float a0 = g_a[e], a1 = g_a[e+1];
    float c0 = g_cc[e], c1 = g_cc[e+1];
    float y0 = 0.f, y1 = 0.f;
    size_t tok0 = (size_t)b*SS + c*CLEN;
    const __nv_bfloat162* Up = (const __nv_bfloat162*)g_uv + ((tok0*(2*EE) + e) >> 1);
    const __nv_bfloat162* Vp = (const __nv_bfloat162*)g_uv + ((tok0*(2*EE) + EE + e) >> 1);
    __nv_bfloat162* uo = (__nv_bfloat162*)g_xc + ((tok0*EE + e) >> 1);
    #pragma unroll 4
    for (int t=0;t<CLEN;t++){
        float2 Uv = __bfloat1622float2(Up[(size_t)t*(2*EE/2)]);
        float2 Vv = __bfloat1622float2(Vp[(size_t)t*(2*EE/2)]);
        float u0 = c0 * Uv.x * sigf(Vv.x);
        float u1 = c1 * Uv.y * sigf(Vv.y);
        uo[(size_t)t*(EE/2)] = __floats2bfloat162_rn(u0, u1);
        y0 = a0*y0 + u0;
        y1 = a1*y1 + u1;
    }
    g_ylast[(((size_t)b<<11)+e)*CH + c]   = y0;
    g_ylast[(((size_t)b<<11)+e+1)*CH + c] = y1;
}
__global__ void scanB_kernel(){
    int id = blockIdx.x*blockDim.x + threadIdx.x;   // 8192
    int e = id & 2047;
    float a = g_a[e];
    float aL = a;
    #pragma unroll
    for (int i=0;i<7;i++) aL *= aL;  // a^128
    float y = 0.f;
    #pragma unroll
    for (int c=0;c<CH;c++){
        g_yinit[id*CH + c] = y;
        y = g_ylast[id*CH + c] + aL*y;
    }
}
__global__ void scanC_kernel(){
    int id = blockIdx.x*blockDim.x + threadIdx.x;   // 65536
    int ep = id & 1023, c = (id >> 10) & (CH-1), b = id >> 14;
    int e = ep*2;
    float a0 = g_a[e], a1 = g_a[e+1];
    float y0 = g_yinit[(((size_t)b<<11)+e)*CH + c];
    float y1 = g_yinit[(((size_t)b<<11)+e+1)*CH + c];
    size_t tok0 = (size_t)b*SS + c*CLEN;
    const __nv_bfloat162* up = (const __nv_bfloat162*)g_xc + ((tok0*EE + e) >> 1);
    const __nv_bfloat162* gp = (const __nv_bfloat162*)g_xpg + ((tok0*(2*EE) + EE + e) >> 1);
    __nv_bfloat162* og = (__nv_bfloat162*)g_xg + ((tok0*EE + e) >> 1);
    #pragma unroll 4
    for (int t=0;t<CLEN;t++){
        float2 uv = __bfloat1622float2(up[(size_t)t*(EE/2)]);
        float2 gv = __bfloat1622float2(gp[(size_t)t*(2*EE/2)]);
        y0 = a0*y0 + uv.x;
        y1 = a1*y1 + uv.y;
        og[(size_t)t*(EE/2)] = __floats2bfloat162_rn(y0*sigf(gv.x), y1*sigf(gv.y));
    }
}

// ---------------- launch ----------------
extern "C" void kernel_launch(void* const* d_in, const int* in_sizes, int n_in,
                              void* d_out, int out_size){
    const float* x         = (const float*)d_in[0];
    const float* ln_g      = (const float*)d_in[1];
    const float* ln_b      = (const float*)d_in[2];
    const float* W_in      = (const float*)d_in[3];
    const float* b_in      = (const float*)d_in[4];
    const float* conv_w    = (const float*)d_in[5];
    const float* conv_b    = (const float*)d_in[6];
    const float* Amat      = (const float*)d_in[7];
    const float* Bmat      = (const float*)d_in[8];
    const float* W_c       = (const float*)d_in[9];
    const float* b_c       = (const float*)d_in[10];
    const float* W_d       = (const float*)d_in[11];
    const float* b_d       = (const float*)d_in[12];
    const float* log_delta = (const float*)d_in[13];
    const float* W_out     = (const float*)d_in[14];
    const float* b_out     = (const float*)d_in[15];
    float* out = (float*)d_out;

    cudaFuncSetAttribute(gemm_kernel<0>, cudaFuncAttributeMaxDynamicSharedMemorySize, GEMM_SMEM);
    cudaFuncSetAttribute(gemm_kernel<1>, cudaFuncAttributeMaxDynamicSharedMemorySize, GEMM_SMEM);
    cudaFuncSetAttribute(gemm_kernel<2>, cudaFuncAttributeMaxDynamicSharedMemorySize, GEMM_SMEM);

    wconv_kernel<<<4096, 256>>>(W_in, W_c, W_d, W_out);
    pre_small<<<8, 256>>>(log_delta, Amat, Bmat, b_c, b_d);
    ln_kernel<<<MM, 256>>>(x, ln_g, ln_b);
    gemm_kernel<0><<<dim3(32,64), 256, GEMM_SMEM>>>(b_in, nullptr, nullptr);
    conv_kernel<<<256, 256>>>(conv_w, conv_b);
    gemm_kernel<1><<<dim3(32,64), 256, GEMM_SMEM>>>(nullptr, nullptr, nullptr);
    scanA_kernel<<<256, 256>>>();
    scanB_kernel<<<32, 256>>>();
    scanC_kernel<<<256, 256>>>();
    gemm_kernel<2><<<dim3(8,64), 256, GEMM_SMEM>>>(b_out, x, out);
}

// round 11
// speedup vs baseline: 1.2414x; 1.0281x over previous
#include <cuda_runtime.h>
#include <cuda_bf16.h>
#include <cstdint>

// Problem dims
#define BB 4
#define SS 2048
#define DD 1024
#define EE 2048
#define NN 16
#define MM (BB*SS)          // 8192 tokens
#define CH 16               // scan chunks per sequence

// ---------------- scratch (device globals; no allocation allowed) ----------
__device__ __align__(256) __nv_bfloat16 g_xln[MM*DD];
__device__ __align__(256) __nv_bfloat16 g_xpg[(size_t)MM*2*EE]; // x_proj (xp|gate)
__device__ __align__(256) __nv_bfloat16 g_xc [(size_t)MM*EE];   // conv+silu out; later reused for cc*u
__device__ __align__(256) __nv_bfloat16 g_uv [(size_t)MM*2*EE]; // (U+bc | V+bd)
__device__ __align__(256) __nv_bfloat16 g_xg [(size_t)MM*EE];   // gated ssm out
__device__ __align__(256) __nv_bfloat16 g_win [(size_t)2*EE*DD];
__device__ __align__(256) __nv_bfloat16 g_wcd [(size_t)2*EE*EE];
__device__ __align__(256) __nv_bfloat16 g_wout[(size_t)DD*EE];
__device__ float g_a[EE];
__device__ float g_cc[EE];
__device__ float g_biascat[2*EE];
__device__ float g_ylast[BB*EE*CH];
__device__ float g_yinit[BB*EE*CH];

// ---------------- helpers ----------------
__device__ __forceinline__ uint32_t smem_u32(const void* p){
    return (uint32_t)__cvta_generic_to_shared(p);
}
__device__ __forceinline__ void cp_async16(uint32_t saddr, const void* gptr){
    asm volatile("cp.async.cg.shared.global [%0], [%1], 16;" :: "r"(saddr), "l"(gptr));
}
__device__ __forceinline__ void cp_commit(){ asm volatile("cp.async.commit_group;"); }
__device__ __forceinline__ void ldsm4(uint32_t& r0,uint32_t& r1,uint32_t& r2,uint32_t& r3,uint32_t addr){
    asm volatile("ldmatrix.sync.aligned.m8n8.x4.shared.b16 {%0,%1,%2,%3}, [%4];"
        : "=r"(r0),"=r"(r1),"=r"(r2),"=r"(r3) : "r"(addr));
}
__device__ __forceinline__ void mma16816(float* c, uint32_t a0,uint32_t a1,uint32_t a2,uint32_t a3,
                                         uint32_t b0,uint32_t b1){
    asm volatile("mma.sync.aligned.m16n8k16.row.col.f32.bf16.bf16.f32 "
        "{%0,%1,%2,%3},{%4,%5,%6,%7},{%8,%9},{%0,%1,%2,%3};"
        : "+f"(c[0]),"+f"(c[1]),"+f"(c[2]),"+f"(c[3])
        : "r"(a0),"r"(a1),"r"(a2),"r"(a3),"r"(b0),"r"(b1));
}
__device__ __forceinline__ float sigf(float x){ return 1.f/(1.f+__expf(-x)); }
__device__ __forceinline__ uint32_t bf2u(__nv_bfloat162 v){
    uint32_t u;
    memcpy(&u, &v, 4);
    return u;
}

// ---------------- precompute: weight bf16 conversion (vectorized) ----------
__global__ void wconv_kernel(const float* __restrict__ win, const float* __restrict__ wc,
                             const float* __restrict__ wd, const float* __restrict__ wout){
    size_t idx = (size_t)blockIdx.x*blockDim.x + threadIdx.x;  // 1048576 threads
    size_t i4 = idx*4;
    auto cv = [](float4 v)->uint2{
        uint2 r;
        r.x = bf2u(__floats2bfloat162_rn(v.x, v.y));
        r.y = bf2u(__floats2bfloat162_rn(v.z, v.w));
        return r;
    };
    *reinterpret_cast<uint2*>(&g_win[i4]) = cv(*reinterpret_cast<const float4*>(&win[i4]));
    *reinterpret_cast<uint2*>(&g_wcd[i4]) = cv(*reinterpret_cast<const float4*>(&wc[i4]));
    *reinterpret_cast<uint2*>(&g_wcd[(size_t)4194304 + i4]) = cv(*reinterpret_cast<const float4*>(&wd[i4]));
    if (i4 < (size_t)DD*EE)
        *reinterpret_cast<uint2*>(&g_wout[i4]) = cv(*reinterpret_cast<const float4*>(&wout[i4]));
}

// ---------------- precompute: a_e, c_e, bias_cat ----------------
__global__ void pre_small(const float* __restrict__ log_delta, const float* __restrict__ Amat,
                          const float* __restrict__ Bmat, const float* __restrict__ bc,
                          const float* __restrict__ bd){
    int e = blockIdx.x*blockDim.x + threadIdx.x;
    if (e < EE){
        float dl = log_delta[e];
        float sp = (dl > 20.f) ? dl : log1pf(expf(dl));
        g_a[e] = expf(-sp);
        float s = 0.f;
        #pragma unroll
        for (int n=0; n<NN; n++) s += Amat[e*NN+n]*Bmat[e*NN+n];
        g_cc[e] = s;
        g_biascat[e]    = bc[e];
        g_biascat[EE+e] = bd[e];
    }
}

// ---------------- layernorm -> bf16 ----------------
__global__ void ln_kernel(const float* __restrict__ x, const float* __restrict__ g,
                          const float* __restrict__ bta){
    int m = blockIdx.x;
    int tid = threadIdx.x;
    const float* row = x + (size_t)m*DD;
    float v[4], s=0.f, s2=0.f;
    #pragma unroll
    for (int i=0;i<4;i++){ v[i]=row[tid+i*256]; s+=v[i]; s2+=v[i]*v[i]; }
    #pragma unroll
    for (int o=16;o;o>>=1){ s += __shfl_xor_sync(~0u,s,o); s2 += __shfl_xor_sync(~0u,s2,o); }
    __shared__ float sh[2][8];
    int w = tid>>5, l = tid&31;
    if (l==0){ sh[0][w]=s; sh[1][w]=s2; }
    __syncthreads();
    s=0.f; s2=0.f;
    #pragma unroll
    for (int j=0;j<8;j++){ s+=sh[0][j]; s2+=sh[1][j]; }
    float mu = s*(1.f/DD);
    float var = s2*(1.f/DD) - mu*mu;
    float rs = rsqrtf(var + 1e-5f);
    #pragma unroll
    for (int i=0;i<4;i++){
        int c = tid+i*256;
        g_xln[(size_t)m*DD + c] = __float2bfloat16((v[i]-mu)*rs*g[c] + bta[c]);
    }
}

// ---------------- GEMM: C[m,n] = sum_k A[m,k]*B[n,k] (+bias)(+resid) -------
// mma.sync, BM=256 x BN=128 block tile, 512 threads (4x4 warp grid, 64x32
// warp tile), 64-wide K chunks, 3-stage cp.async pipeline, 1 barrier/chunk.
// MODE 0: A=g_xln(K=1024) B=g_win  -> g_xpg bf16, bias=param
// MODE 1: A=g_xc (K=2048) B=g_wcd  -> g_uv  bf16, bias=g_biascat
// MODE 2: A=g_xg (K=2048) B=g_wout -> fp32 out, bias=param, +resid
#define SD 72u                           // padded K-stride in bf16 (conflict-free ldsm)
#define A_STAGE_B (256u*SD*2u)           // 36864
#define B_STAGE_B (128u*SD*2u)           // 18432
#define STAGE_TOT (A_STAGE_B + B_STAGE_B) // 55296
#define GEMM_SMEM (3*STAGE_TOT)          // 165888 bytes

template<int MODE>
__global__ __launch_bounds__(512,1) void gemm_kernel(const float* __restrict__ bias_p,
                                                     const float* __restrict__ resid,
                                                     float* __restrict__ outf){
    constexpr int N_ = (MODE==2)?1024:4096;
    constexpr int K_ = (MODE==0)?1024:2048;
    constexpr int KT = K_/64;
    const __nv_bfloat16* A  = (MODE==0)? g_xln : (MODE==1)? g_xc : g_xg;
    const __nv_bfloat16* Bw = (MODE==0)? g_win : (MODE==1)? g_wcd : g_wout;
    __nv_bfloat16* Cb = (MODE==0)? g_xpg : g_uv;
    const float* bias = (MODE==1)? g_biascat : bias_p;

    extern __shared__ __nv_bfloat16 smem[];
    const uint32_t sbase = smem_u32(smem);

    const int tid = threadIdx.x;
    const int lane = tid & 31, warp = tid >> 5;
    const int wm = warp >> 2, wn = warp & 3;        // 4 x 4 warp grid
    const int bm = blockIdx.y * 256, bn = blockIdx.x * 128;

    float acc[4][4][4];
    #pragma unroll
    for (int i=0;i<4;i++) for (int j=0;j<4;j++) for (int q=0;q<4;q++) acc[i][j][q]=0.f;

    // chunk loader: A 256x64 (4 ops/thread) + B 128x64 (2 ops/thread)
    auto load_tile = [&](int kt, int s){
        uint32_t a0 = sbase + (uint32_t)s*STAGE_TOT;
        uint32_t b0 = a0 + A_STAGE_B;
        #pragma unroll
        for (int h=0; h<4; h++){
            int c = tid + h*512;
            int row = c >> 3, seg = (c & 7) * 8;
            cp_async16(a0 + (uint32_t)((row*SD + seg)*2),
                       A + (size_t)(bm+row)*K_ + kt*64 + seg);
        }
        #pragma unroll
        for (int h=0; h<2; h++){
            int c = tid + h*512;
            int row = c >> 3, seg = (c & 7) * 8;
            cp_async16(b0 + (uint32_t)((row*SD + seg)*2),
                       Bw + (size_t)(bn+row)*K_ + kt*64 + seg);
        }
        cp_commit();
    };

    const int la_row = lane & 15;
    const int la_c8  = (lane >> 4) << 3;
    const int lb_row = ((lane >> 4) << 3) + (lane & 7);
    const int lb_c8  = ((lane >> 3) & 1) << 3;

    // prologue: fill 2 of 3 stages
    load_tile(0,0);
    if (KT > 1) load_tile(1,1);

    for (int kt=0; kt<KT; kt++){
        if (KT-1-kt >= 1) { asm volatile("cp.async.wait_group 1;" ::: "memory"); }
        else              { asm volatile("cp.async.wait_group 0;" ::: "memory"); }
        __syncthreads();
        if (kt+2 < KT){
            int s = (kt+2)%3;
            load_tile(kt+2, s);
        }

        uint32_t baseA = sbase + (uint32_t)(kt%3)*STAGE_TOT;
        uint32_t baseB = baseA + A_STAGE_B;
        #pragma unroll
        for (int k16=0;k16<4;k16++){
            int kb = k16*16;
            uint32_t a[4][4], bfr[2][4];
            #pragma unroll
            for (int i=0;i<4;i++){
                uint32_t ad = baseA + (uint32_t)(((wm*64 + i*16 + la_row)*SD + kb + la_c8)*2);
                ldsm4(a[i][0],a[i][1],a[i][2],a[i][3], ad);
            }
            #pragma unroll
            for (int jp=0;jp<2;jp++){
                uint32_t bd = baseB + (uint32_t)(((wn*32 + jp*16 + lb_row)*SD + kb + lb_c8)*2);
                ldsm4(bfr[jp][0],bfr[jp][1],bfr[jp][2],bfr[jp][3], bd);
            }
            #pragma unroll
            for (int i=0;i<4;i++){
                #pragma unroll
                for (int j=0;j<4;j++){
                    int jp=j>>1, o=(j&1)*2;
                    mma16816(acc[i][j], a[i][0],a[i][1],a[i][2],a[i][3], bfr[jp][o], bfr[jp][o+1]);
                }
            }
        }
    }

    // epilogue
    const int ro = lane >> 2, co = (lane & 3) * 2;
    #pragma unroll
    for (int i=0;i<4;i++){
        #pragma unroll
        for (int j=0;j<4;j++){
            int r  = bm + wm*64 + i*16 + ro;
            int cc = bn + wn*32 + j*8 + co;
            float b0 = bias[cc], b1 = bias[cc+1];
            float v0 = acc[i][j][0]+b0, v1 = acc[i][j][1]+b1;
            float v2 = acc[i][j][2]+b0, v3 = acc[i][j][3]+b1;
            if (MODE==2){
                size_t o0 = (size_t)r*N_ + cc;
                size_t o1 = (size_t)(r+8)*N_ + cc;
                outf[o0]   = v0 + resid[o0];
                outf[o0+1] = v1 + resid[o0+1];
                outf[o1]   = v2 + resid[o1];
                outf[o1+1] = v3 + resid[o1+1];
            } else {
                *reinterpret_cast<__nv_bfloat162*>(&Cb[(size_t)r*N_ + cc])
                    = __floats2bfloat162_rn(v0, v1);
                *reinterpret_cast<__nv_bfloat162*>(&Cb[(size_t)(r+8)*N_ + cc])
                    = __floats2bfloat162_rn(v2, v3);
            }
        }
    }
}

// ---------------- causal depthwise conv K=4 + silu ----------------
__global__ void conv_kernel(const float* __restrict__ cw, const float* __restrict__ cb){
    int id = blockIdx.x*blockDim.x + threadIdx.x;     // 65536
    int ep = id & 1023;
    int c  = (id >> 10) & 15;
    int b  = id >> 14;
    int e  = ep*2;
    float w[4][2];
    #pragma unroll
    for (int k=0;k<4;k++){ w[k][0]=cw[e*4+k]; w[k][1]=cw[(e+1)*4+k]; }
    float bi0 = cb[e], bi1 = cb[e+1];
    const __nv_bfloat162* XP = reinterpret_cast<const __nv_bfloat162*>(g_xpg);
    __nv_bfloat162* XC = reinterpret_cast<__nv_bfloat162*>(g_xc);
    int s0 = c*128;
    float2 win[3];
    #pragma unroll
    for (int k=0;k<3;k++){
        int s = s0 - 3 + k;
        if (s >= 0){
            __nv_bfloat162 t = XP[((size_t)(b*SS+s)*(2*EE) + e) >> 1];
            win[k] = make_float2(__low2float(t), __high2float(t));
        } else win[k] = make_float2(0.f, 0.f);
    }
    #pragma unroll 4
    for (int s=s0; s<s0+128; s++){
        __nv_bfloat162 t = XP[((size_t)(b*SS+s)*(2*EE) + e) >> 1];
        float2 cur = make_float2(__low2float(t), __high2float(t));
        float ax = bi0 + w[0][0]*win[0].x + w[1][0]*win[1].x + w[2][0]*win[2].x + w[3][0]*cur.x;
        float ay = bi1 + w[0][1]*win[0].y + w[1][1]*win[1].y + w[2][1]*win[2].y + w[3][1]*cur.y;
        ax = ax * sigf(ax);
        ay = ay * sigf(ay);
        XC[((size_t)(b*SS+s)*EE + e) >> 1] = __floats2bfloat162_rn(ax, ay);
        win[0]=win[1]; win[1]=win[2]; win[2]=cur;
    }
}

// ---------------- chunked linear scan (pair-vectorized, 16 chunks of 128) --
// y_t = a*y_{t-1} + cu_t,  cu_t = cc*U*sigmoid(V). scanA stores cu into g_xc.
#define CLEN (SS/CH)   // 128
__global__ void scanA_kernel(){
    int id = blockIdx.x*blockDim.x + threadIdx.x;   // 65536
    int ep = id & 1023, c = (id >> 10) & (CH-1), b = id >> 14;
    int e = ep*2;
    float a0 = g_a[e], a1 = g_a[e+1];
    float c0 = g_cc[e], c1 = g_cc[e+1];
    float y0 = 0.f, y1 = 0.f;
    size_t tok0 = (size_t)b*SS + c*CLEN;
    const __nv_bfloat162* Up = (const __nv_bfloat162*)g_uv + ((tok0*(2*EE) + e) >> 1);
    const __nv_bfloat162* Vp = (const __nv_bfloat162*)g_uv + ((tok0*(2*EE) + EE + e) >> 1);
    __nv_bfloat162* uo = (__nv_bfloat162*)g_xc + ((tok0*EE + e) >> 1);
    #pragma unroll 4
    for (int t=0;t<CLEN;t++){
        float2 Uv = __bfloat1622float2(Up[(size_t)t*(2*EE/2)]);
        float2 Vv = __bfloat1622float2(Vp[(size_t)t*(2*EE/2)]);
        float u0 = c0 * Uv.x * sigf(Vv.x);
        float u1 = c1 * Uv.y * sigf(Vv.y);
        uo[(size_t)t*(EE/2)] = __floats2bfloat162_rn(u0, u1);
        y0 = a0*y0 + u0;
        y1 = a1*y1 + u1;
    }
    g_ylast[(((size_t)b<<11)+e)*CH + c]   = y0;
    g_ylast[(((size_t)b<<11)+e+1)*CH + c] = y1;
}
__global__ void scanB_kernel(){
    int id = blockIdx.x*blockDim.x + threadIdx.x;   // 8192
    int e = id & 2047;
    float a = g_a[e];
    float aL = a;
    #pragma unroll
    for (int i=0;i<7;i++) aL *= aL;  // a^128
    float y = 0.f;
    #pragma unroll
    for (int c=0;c<CH;c++){
        g_yinit[id*CH + c] = y;
        y = g_ylast[id*CH + c] + aL*y;
    }
}
__global__ void scanC_kernel(){
    int id = blockIdx.x*blockDim.x + threadIdx.x;   // 65536
    int ep = id & 1023, c = (id >> 10) & (CH-1), b = id >> 14;
    int e = ep*2;
    float a0 = g_a[e], a1 = g_a[e+1];
    float y0 = g_yinit[(((size_t)b<<11)+e)*CH + c];
    float y1 = g_yinit[(((size_t)b<<11)+e+1)*CH + c];
    size_t tok0 = (size_t)b*SS + c*CLEN;
    const __nv_bfloat162* up = (const __nv_bfloat162*)g_xc + ((tok0*EE + e) >> 1);
    const __nv_bfloat162* gp = (const __nv_bfloat162*)g_xpg + ((tok0*(2*EE) + EE + e) >> 1);
    __nv_bfloat162* og = (__nv_bfloat162*)g_xg + ((tok0*EE + e) >> 1);
    #pragma unroll 4
    for (int t=0;t<CLEN;t++){
        float2 uv = __bfloat1622float2(up[(size_t)t*(EE/2)]);
        float2 gv = __bfloat1622float2(gp[(size_t)t*(2*EE/2)]);
        y0 = a0*y0 + uv.x;
        y1 = a1*y1 + uv.y;
        og[(size_t)t*(EE/2)] = __floats2bfloat162_rn(y0*sigf(gv.x), y1*sigf(gv.y));
    }
}

// ---------------- launch ----------------
extern "C" void kernel_launch(void* const* d_in, const int* in_sizes, int n_in,
                              void* d_out, int out_size){
    const float* x         = (const float*)d_in[0];
    const float* ln_g      = (const float*)d_in[1];
    const float* ln_b      = (const float*)d_in[2];
    const float* W_in      = (const float*)d_in[3];
    const float* b_in      = (const float*)d_in[4];
    const float* conv_w    = (const float*)d_in[5];
    const float* conv_b    = (const float*)d_in[6];
    const float* Amat      = (const float*)d_in[7];
    const float* Bmat      = (const float*)d_in[8];
    const float* W_c       = (const float*)d_in[9];
    const float* b_c       = (const float*)d_in[10];
    const float* W_d       = (const float*)d_in[11];
    const float* b_d       = (const float*)d_in[12];
    const float* log_delta = (const float*)d_in[13];
    const float* W_out     = (const float*)d_in[14];
    const float* b_out     = (const float*)d_in[15];
    float* out = (float*)d_out;

    cudaFuncSetAttribute(gemm_kernel<0>, cudaFuncAttributeMaxDynamicSharedMemorySize, GEMM_SMEM);
    cudaFuncSetAttribute(gemm_kernel<1>, cudaFuncAttributeMaxDynamicSharedMemorySize, GEMM_SMEM);
    cudaFuncSetAttribute(gemm_kernel<2>, cudaFuncAttributeMaxDynamicSharedMemorySize, GEMM_SMEM);

    wconv_kernel<<<4096, 256>>>(W_in, W_c, W_d, W_out);
    pre_small<<<8, 256>>>(log_delta, Amat, Bmat, b_c, b_d);
    ln_kernel<<<MM, 256>>>(x, ln_g, ln_b);
    gemm_kernel<0><<<dim3(32,32), 512, GEMM_SMEM>>>(b_in, nullptr, nullptr);
    conv_kernel<<<256, 256>>>(conv_w, conv_b);
    gemm_kernel<1><<<dim3(32,32), 512, GEMM_SMEM>>>(nullptr, nullptr, nullptr);
    scanA_kernel<<<256, 256>>>();
    scanB_kernel<<<32, 256>>>();
    scanC_kernel<<<256, 256>>>();
    gemm_kernel<2><<<dim3(8,32), 512, GEMM_SMEM>>>(b_out, x, out);
}

// round 12
// speedup vs baseline: 1.2899x; 1.0391x over previous
#include <cuda_runtime.h>
#include <cuda_bf16.h>
#include <cuda_fp8.h>
#include <cstdint>

// Problem dims
#define BB 4
#define SS 2048
#define DD 1024
#define EE 2048
#define NN 16
#define MM (BB*SS)          // 8192 tokens
#define CH 16               // scan chunks per sequence

// ---------------- scratch (device globals; no allocation allowed) ----------
__device__ __align__(256) uint8_t g_xln8[(size_t)MM*DD];         // fp8 ln out
__device__ __align__(256) __nv_bfloat16 g_xpg[(size_t)MM*2*EE];  // x_proj (xp|gate) bf16
__device__ __align__(256) uint8_t g_xc8[(size_t)MM*EE];          // fp8 conv+silu out
__device__ __align__(256) __nv_bfloat16 g_cu [(size_t)MM*EE];    // cc*u (fused gemm1 epilogue)
__device__ __align__(256) __nv_bfloat16 g_xg [(size_t)MM*EE];    // gated ssm out bf16
__device__ __align__(256) uint8_t g_win8[(size_t)2*EE*DD];       // fp8 W_in
__device__ __align__(256) uint8_t g_wcd8[(size_t)2*EE*EE];       // fp8 interleaved W_c/W_d rows
__device__ __align__(256) __nv_bfloat16 g_wout[(size_t)DD*EE];   // bf16 W_out
__device__ float g_a[EE];
__device__ float g_cc[EE];
__device__ float g_biascat[2*EE];   // interleaved: [2f]=b_c[f], [2f+1]=b_d[f]
__device__ float g_ylast[BB*EE*CH];
__device__ float g_yinit[BB*EE*CH];

// ---------------- helpers ----------------
__device__ __forceinline__ uint32_t smem_u32(const void* p){
    return (uint32_t)__cvta_generic_to_shared(p);
}
__device__ __forceinline__ void cp_async16(uint32_t saddr, const void* gptr){
    asm volatile("cp.async.cg.shared.global [%0], [%1], 16;" :: "r"(saddr), "l"(gptr));
}
__device__ __forceinline__ void cp_commit(){ asm volatile("cp.async.commit_group;"); }
__device__ __forceinline__ void ldsm4(uint32_t& r0,uint32_t& r1,uint32_t& r2,uint32_t& r3,uint32_t addr){
    asm volatile("ldmatrix.sync.aligned.m8n8.x4.shared.b16 {%0,%1,%2,%3}, [%4];"
        : "=r"(r0),"=r"(r1),"=r"(r2),"=r"(r3) : "r"(addr));
}
__device__ __forceinline__ void mma_bf16(float* c, uint32_t a0,uint32_t a1,uint32_t a2,uint32_t a3,
                                         uint32_t b0,uint32_t b1){
    asm volatile("mma.sync.aligned.m16n8k16.row.col.f32.bf16.bf16.f32 "
        "{%0,%1,%2,%3},{%4,%5,%6,%7},{%8,%9},{%0,%1,%2,%3};"
        : "+f"(c[0]),"+f"(c[1]),"+f"(c[2]),"+f"(c[3])
        : "r"(a0),"r"(a1),"r"(a2),"r"(a3),"r"(b0),"r"(b1));
}
__device__ __forceinline__ void mma_fp8(float* c, uint32_t a0,uint32_t a1,uint32_t a2,uint32_t a3,
                                        uint32_t b0,uint32_t b1){
    asm volatile("mma.sync.aligned.m16n8k32.row.col.f32.e4m3.e4m3.f32 "
        "{%0,%1,%2,%3},{%4,%5,%6,%7},{%8,%9},{%0,%1,%2,%3};"
        : "+f"(c[0]),"+f"(c[1]),"+f"(c[2]),"+f"(c[3])
        : "r"(a0),"r"(a1),"r"(a2),"r"(a3),"r"(b0),"r"(b1));
}
__device__ __forceinline__ float sigf(float x){ return 1.f/(1.f+__expf(-x)); }
__device__ __forceinline__ uint32_t bf2u(__nv_bfloat162 v){
    uint32_t u; memcpy(&u, &v, 4); return u;
}
__device__ __forceinline__ uint16_t f2fp8x2(float a, float b){
    return (uint16_t)__nv_cvt_float2_to_fp8x2(make_float2(a,b), __NV_SATFINITE, __NV_E4M3);
}
__device__ __forceinline__ uint32_t f4fp8x4(float4 v){
    uint32_t lo = f2fp8x2(v.x, v.y);
    uint32_t hi = f2fp8x2(v.z, v.w);
    return lo | (hi << 16);
}

// ---------------- precompute: weight conversion ----------------
// fp8 W_in, fp8 interleaved W_c/W_d (row 2f = W_c[f], row 2f+1 = W_d[f]), bf16 W_out
__global__ void wconv_kernel(const float* __restrict__ win, const float* __restrict__ wc,
                             const float* __restrict__ wd, const float* __restrict__ wout){
    size_t idx = (size_t)blockIdx.x*blockDim.x + threadIdx.x;  // 1048576 threads
    size_t i4 = idx*4;
    // W_in: 4194304 elems -> fp8
    *reinterpret_cast<uint32_t*>(&g_win8[i4]) = f4fp8x4(*reinterpret_cast<const float4*>(&win[i4]));
    // W_c / W_d interleaved fp8
    {
        size_t f = i4 >> 11;          // row in [0,2048)
        size_t k = i4 & 2047;
        *reinterpret_cast<uint32_t*>(&g_wcd8[(2*f)*EE + k])   = f4fp8x4(*reinterpret_cast<const float4*>(&wc[i4]));
        *reinterpret_cast<uint32_t*>(&g_wcd8[(2*f+1)*EE + k]) = f4fp8x4(*reinterpret_cast<const float4*>(&wd[i4]));
    }
    // W_out -> bf16
    if (i4 < (size_t)DD*EE){
        float4 v = *reinterpret_cast<const float4*>(&wout[i4]);
        uint2 r;
        r.x = bf2u(__floats2bfloat162_rn(v.x, v.y));
        r.y = bf2u(__floats2bfloat162_rn(v.z, v.w));
        *reinterpret_cast<uint2*>(&g_wout[i4]) = r;
    }
}

// ---------------- precompute: a_e, c_e, interleaved bias ----------------
__global__ void pre_small(const float* __restrict__ log_delta, const float* __restrict__ Amat,
                          const float* __restrict__ Bmat, const float* __restrict__ bc,
                          const float* __restrict__ bd){
    int e = blockIdx.x*blockDim.x + threadIdx.x;
    if (e < EE){
        float dl = log_delta[e];
        float sp = (dl > 20.f) ? dl : log1pf(expf(dl));
        g_a[e] = expf(-sp);
        float s = 0.f;
        #pragma unroll
        for (int n=0; n<NN; n++) s += Amat[e*NN+n]*Bmat[e*NN+n];
        g_cc[e] = s;
        g_biascat[2*e]   = bc[e];
        g_biascat[2*e+1] = bd[e];
    }
}

// ---------------- layernorm -> fp8 ----------------
__global__ void ln_kernel(const float* __restrict__ x, const float* __restrict__ g,
                          const float* __restrict__ bta){
    int m = blockIdx.x;
    int tid = threadIdx.x;
    const float* row = x + (size_t)m*DD;
    float v[4], s=0.f, s2=0.f;
    #pragma unroll
    for (int i=0;i<4;i++){ v[i]=row[tid+i*256]; s+=v[i]; s2+=v[i]*v[i]; }
    #pragma unroll
    for (int o=16;o;o>>=1){ s += __shfl_xor_sync(~0u,s,o); s2 += __shfl_xor_sync(~0u,s2,o); }
    __shared__ float sh[2][8];
    int w = tid>>5, l = tid&31;
    if (l==0){ sh[0][w]=s; sh[1][w]=s2; }
    __syncthreads();
    s=0.f; s2=0.f;
    #pragma unroll
    for (int j=0;j<8;j++){ s+=sh[0][j]; s2+=sh[1][j]; }
    float mu = s*(1.f/DD);
    float var = s2*(1.f/DD) - mu*mu;
    float rs = rsqrtf(var + 1e-5f);
    #pragma unroll
    for (int i=0;i<4;i++){
        int c = tid+i*256;
        float val = (v[i]-mu)*rs*g[c] + bta[c];
        g_xln8[(size_t)m*DD + c] = (uint8_t)__nv_cvt_float_to_fp8(val, __NV_SATFINITE, __NV_E4M3);
    }
}

// ---------------- FP8 GEMM: C[m,n] = sum_k A[m,k]*B[n,k] ------------------
// mma.sync m16n8k32 e4m3, BM=256 x BN=128, 512 threads (4x4 warps, 64x32 warp
// tile), 64-byte K chunks, 4-stage cp.async pipeline.
// MODE 0: A=g_xln8 (K=1024) B=g_win8 -> g_xpg bf16 (+b_in)
// MODE 1: A=g_xc8  (K=2048) B=g_wcd8 -> g_cu  bf16 fused cc*(U+bc)*sig(V+bd)
#define SDB 80u                         // padded row stride (bytes)
#define A_ST (256u*SDB)                 // 20480
#define B_ST (128u*SDB)                 // 10240
#define STT (A_ST + B_ST)               // 30720
#define FP8_SMEM (4*STT)                // 122880

template<int MODE>
__global__ __launch_bounds__(512,1) void gemm_fp8(const float* __restrict__ bias_p){
    constexpr int K_ = (MODE==0)?1024:2048;   // bytes per row (== elements)
    constexpr int KT = K_/64;
    const uint8_t* A  = (MODE==0)? g_xln8 : g_xc8;
    const uint8_t* Bw = (MODE==0)? g_win8 : g_wcd8;

    extern __shared__ uint8_t smem[];
    const uint32_t sbase = smem_u32(smem);

    const int tid = threadIdx.x;
    const int lane = tid & 31, warp = tid >> 5;
    const int wm = warp >> 2, wn = warp & 3;        // 4 x 4 warp grid
    const int bm = blockIdx.y * 256, bn = blockIdx.x * 128;

    float acc[4][4][4];
    #pragma unroll
    for (int i=0;i<4;i++) for (int j=0;j<4;j++) for (int q=0;q<4;q++) acc[i][j][q]=0.f;

    // chunk loader: A 256 rows x 64B (2 segs/thread) + B 128 rows x 64B (1 seg/thread)
    auto load_tile = [&](int kt, int s){
        uint32_t a0 = sbase + (uint32_t)s*STT;
        uint32_t b0 = a0 + A_ST;
        #pragma unroll
        for (int h=0; h<2; h++){
            int c = tid + h*512;
            int row = c >> 2, seg = (c & 3) * 16;
            cp_async16(a0 + (uint32_t)(row*SDB + seg),
                       A + (size_t)(bm+row)*K_ + kt*64 + seg);
        }
        {
            int row = tid >> 2, seg = (tid & 3) * 16;
            cp_async16(b0 + (uint32_t)(row*SDB + seg),
                       Bw + (size_t)(bn+row)*K_ + kt*64 + seg);
        }
        cp_commit();
    };

    const int la_row = lane & 15;
    const int la_c16 = (lane >> 4) * 16;                       // byte offset
    const int lb_row = ((lane >> 4) << 3) + (lane & 7);
    const int lb_c16 = ((lane >> 3) & 1) * 16;                 // byte offset

    // prologue: fill 3 of 4 stages
    load_tile(0,0); load_tile(1,1); load_tile(2,2);

    for (int kt=0; kt<KT; kt++){
        int rem = KT-1-kt;
        if (rem >= 2)      { asm volatile("cp.async.wait_group 2;" ::: "memory"); }
        else if (rem == 1) { asm volatile("cp.async.wait_group 1;" ::: "memory"); }
        else               { asm volatile("cp.async.wait_group 0;" ::: "memory"); }
        __syncthreads();
        if (kt+3 < KT) load_tile(kt+3, (kt+3)&3);

        uint32_t baseA = sbase + (uint32_t)(kt&3)*STT;
        uint32_t baseB = baseA + A_ST;
        #pragma unroll
        for (int kb=0; kb<2; kb++){                  // two k32 steps per 64B chunk
            int cb = kb*32;
            uint32_t a[4][4], bfr[2][4];
            #pragma unroll
            for (int i=0;i<4;i++){
                uint32_t ad = baseA + (uint32_t)((wm*64 + i*16 + la_row)*SDB + cb + la_c16);
                ldsm4(a[i][0],a[i][1],a[i][2],a[i][3], ad);
            }
            #pragma unroll
            for (int jp=0;jp<2;jp++){
                uint32_t bd = baseB + (uint32_t)((wn*32 + jp*16 + lb_row)*SDB + cb + lb_c16);
                ldsm4(bfr[jp][0],bfr[jp][1],bfr[jp][2],bfr[jp][3], bd);
            }
            #pragma unroll
            for (int i=0;i<4;i++){
                #pragma unroll
                for (int j=0;j<4;j++){
                    int jp=j>>1, o=(j&1)*2;
                    mma_fp8(acc[i][j], a[i][0],a[i][1],a[i][2],a[i][3], bfr[jp][o], bfr[jp][o+1]);
                }
            }
        }
    }

    // epilogue
    const int ro = lane >> 2, co = (lane & 3) * 2;
    #pragma unroll
    for (int i=0;i<4;i++){
        #pragma unroll
        for (int j=0;j<4;j++){
            int r  = bm + wm*64 + i*16 + ro;
            int cc = bn + wn*32 + j*8 + co;
            if (MODE == 0){
                float b0 = bias_p[cc], b1 = bias_p[cc+1];
                *reinterpret_cast<__nv_bfloat162*>(&g_xpg[(size_t)r*4096 + cc])
                    = __floats2bfloat162_rn(acc[i][j][0]+b0, acc[i][j][1]+b1);
                *reinterpret_cast<__nv_bfloat162*>(&g_xpg[(size_t)(r+8)*4096 + cc])
                    = __floats2bfloat162_rn(acc[i][j][2]+b0, acc[i][j][3]+b1);
            } else {
                // cols (cc, cc+1) = (U_f, V_f) with f = cc/2 (interleaved weights)
                float b0 = g_biascat[cc], b1 = g_biascat[cc+1];
                int f = cc >> 1;
                float cf = g_cc[f];
                float u0 = cf * (acc[i][j][0]+b0) * sigf(acc[i][j][1]+b1);
                float u1 = cf * (acc[i][j][2]+b0) * sigf(acc[i][j][3]+b1);
                g_cu[(size_t)r*EE + f]     = __float2bfloat16(u0);
                g_cu[(size_t)(r+8)*EE + f] = __float2bfloat16(u1);
            }
        }
    }
}

// ---------------- bf16 GEMM (MODE2 only): out = xg @ W_out^T + b + resid ---
#define SD 72u                           // padded K-stride in bf16
#define A_STAGE_B (256u*SD*2u)
#define B_STAGE_B (128u*SD*2u)
#define STAGE_TOT (A_STAGE_B + B_STAGE_B)
#define BF16_SMEM (3*STAGE_TOT)          // 165888

__global__ __launch_bounds__(512,1) void gemm_out(const float* __restrict__ bias_p,
                                                  const float* __restrict__ resid,
                                                  float* __restrict__ outf){
    constexpr int N_ = 1024;
    constexpr int K_ = 2048;
    constexpr int KT = K_/64;
    const __nv_bfloat16* A  = g_xg;
    const __nv_bfloat16* Bw = g_wout;

    extern __shared__ uint8_t smemb[];
    const uint32_t sbase = smem_u32(smemb);

    const int tid = threadIdx.x;
    const int lane = tid & 31, warp = tid >> 5;
    const int wm = warp >> 2, wn = warp & 3;
    const int bm = blockIdx.y * 256, bn = blockIdx.x * 128;

    float acc[4][4][4];
    #pragma unroll
    for (int i=0;i<4;i++) for (int j=0;j<4;j++) for (int q=0;q<4;q++) acc[i][j][q]=0.f;

    auto load_tile = [&](int kt, int s){
        uint32_t a0 = sbase + (uint32_t)s*STAGE_TOT;
        uint32_t b0 = a0 + A_STAGE_B;
        #pragma unroll
        for (int h=0; h<4; h++){
            int c = tid + h*512;
            int row = c >> 3, seg = (c & 7) * 8;
            cp_async16(a0 + (uint32_t)((row*SD + seg)*2),
                       A + (size_t)(bm+row)*K_ + kt*64 + seg);
        }
        #pragma unroll
        for (int h=0; h<2; h++){
            int c = tid + h*512;
            int row = c >> 3, seg = (c & 7) * 8;
            cp_async16(b0 + (uint32_t)((row*SD + seg)*2),
                       Bw + (size_t)(bn+row)*K_ + kt*64 + seg);
        }
        cp_commit();
    };

    const int la_row = lane & 15;
    const int la_c8  = (lane >> 4) << 3;
    const int lb_row = ((lane >> 4) << 3) + (lane & 7);
    const int lb_c8  = ((lane >> 3) & 1) << 3;

    load_tile(0,0); load_tile(1,1);

    for (int kt=0; kt<KT; kt++){
        if (KT-1-kt >= 1) { asm volatile("cp.async.wait_group 1;" ::: "memory"); }
        else              { asm volatile("cp.async.wait_group 0;" ::: "memory"); }
        __syncthreads();
        if (kt+2 < KT) load_tile(kt+2, (kt+2)%3);

        uint32_t baseA = sbase + (uint32_t)(kt%3)*STAGE_TOT;
        uint32_t baseB = baseA + A_STAGE_B;
        #pragma unroll
        for (int k16=0;k16<4;k16++){
            int kb = k16*16;
            uint32_t a[4][4], bfr[2][4];
            #pragma unroll
            for (int i=0;i<4;i++){
                uint32_t ad = baseA + (uint32_t)(((wm*64 + i*16 + la_row)*SD + kb + la_c8)*2);
                ldsm4(a[i][0],a[i][1],a[i][2],a[i][3], ad);
            }
            #pragma unroll
            for (int jp=0;jp<2;jp++){
                uint32_t bd = baseB + (uint32_t)(((wn*32 + jp*16 + lb_row)*SD + kb + lb_c8)*2);
                ldsm4(bfr[jp][0],bfr[jp][1],bfr[jp][2],bfr[jp][3], bd);
            }
            #pragma unroll
            for (int i=0;i<4;i++){
                #pragma unroll
                for (int j=0;j<4;j++){
                    int jp=j>>1, o=(j&1)*2;
                    mma_bf16(acc[i][j], a[i][0],a[i][1],a[i][2],a[i][3], bfr[jp][o], bfr[jp][o+1]);
                }
            }
        }
    }

    const int ro = lane >> 2, co = (lane & 3) * 2;
    #pragma unroll
    for (int i=0;i<4;i++){
        #pragma unroll
        for (int j=0;j<4;j++){
            int r  = bm + wm*64 + i*16 + ro;
            int cc = bn + wn*32 + j*8 + co;
            float b0 = bias_p[cc], b1 = bias_p[cc+1];
            size_t o0 = (size_t)r*N_ + cc;
            size_t o1 = (size_t)(r+8)*N_ + cc;
            outf[o0]   = acc[i][j][0]+b0 + resid[o0];
            outf[o0+1] = acc[i][j][1]+b1 + resid[o0+1];
            outf[o1]   = acc[i][j][2]+b0 + resid[o1];
            outf[o1+1] = acc[i][j][3]+b1 + resid[o1+1];
        }
    }
}

// ---------------- causal depthwise conv K=4 + silu -> fp8 ----------------
__global__ void conv_kernel(const float* __restrict__ cw, const float* __restrict__ cb){
    int id = blockIdx.x*blockDim.x + threadIdx.x;     // 65536
    int ep = id & 1023;
    int c  = (id >> 10) & 15;
    int b  = id >> 14;
    int e  = ep*2;
    float w[4][2];
    #pragma unroll
    for (int k=0;k<4;k++){ w[k][0]=cw[e*4+k]; w[k][1]=cw[(e+1)*4+k]; }
    float bi0 = cb[e], bi1 = cb[e+1];
    const __nv_bfloat162* XP = reinterpret_cast<const __nv_bfloat162*>(g_xpg);
    uint16_t* XC = reinterpret_cast<uint16_t*>(g_xc8);
    int s0 = c*128;
    float2 win[3];
    #pragma unroll
    for (int k=0;k<3;k++){
        int s = s0 - 3 + k;
        if (s >= 0){
            __nv_bfloat162 t = XP[((size_t)(b*SS+s)*(2*EE) + e) >> 1];
            win[k] = make_float2(__low2float(t), __high2float(t));
        } else win[k] = make_float2(0.f, 0.f);
    }
    #pragma unroll 4
    for (int s=s0; s<s0+128; s++){
        __nv_bfloat162 t = XP[((size_t)(b*SS+s)*(2*EE) + e) >> 1];
        float2 cur = make_float2(__low2float(t), __high2float(t));
        float ax = bi0 + w[0][0]*win[0].x + w[1][0]*win[1].x + w[2][0]*win[2].x + w[3][0]*cur.x;
        float ay = bi1 + w[0][1]*win[0].y + w[1][1]*win[1].y + w[2][1]*win[2].y + w[3][1]*cur.y;
        ax = ax * sigf(ax);
        ay = ay * sigf(ay);
        XC[((size_t)(b*SS+s)*EE + e) >> 1] = f2fp8x2(ax, ay);
        win[0]=win[1]; win[1]=win[2]; win[2]=cur;
    }
}

// ---------------- chunked linear scan ----------------
// y_t = a*y_{t-1} + cu_t; cu precomputed by gemm_fp8<1> epilogue into g_cu.
#define CLEN (SS/CH)   // 128
__global__ void scanA_kernel(){
    int id = blockIdx.x*blockDim.x + threadIdx.x;   // 65536
    int ep = id & 1023, c = (id >> 10) & (CH-1), b = id >> 14;
    int e = ep*2;
    float a0 = g_a[e], a1 = g_a[e+1];
    float y0 = 0.f, y1 = 0.f;
    size_t tok0 = (size_t)b*SS + c*CLEN;
    const __nv_bfloat162* Up = (const __nv_bfloat162*)g_cu + ((tok0*EE + e) >> 1);
    #pragma unroll 4
    for (int t=0;t<CLEN;t++){
        float2 uv = __bfloat1622float2(Up[(size_t)t*(EE/2)]);
        y0 = a0*y0 + uv.x;
        y1 = a1*y1 + uv.y;
    }
    g_ylast[(((size_t)b<<11)+e)*CH + c]   = y0;
    g_ylast[(((size_t)b<<11)+e+1)*CH + c] = y1;
}
__global__ void scanB_kernel(){
    int id = blockIdx.x*blockDim.x + threadIdx.x;   // 8192
    int e = id & 2047;
    float a = g_a[e];
    float aL = a;
    #pragma unroll
    for (int i=0;i<7;i++) aL *= aL;  // a^128
    float y = 0.f;
    #pragma unroll
    for (int c=0;c<CH;c++){
        g_yinit[id*CH + c] = y;
        y = g_ylast[id*CH + c] + aL*y;
    }
}
__global__ void scanC_kernel(){
    int id = blockIdx.x*blockDim.x + threadIdx.x;   // 65536
    int ep = id & 1023, c = (id >> 10) & (CH-1), b = id >> 14;
    int e = ep*2;
    float a0 = g_a[e], a1 = g_a[e+1];
    float y0 = g_yinit[(((size_t)b<<11)+e)*CH + c];
    float y1 = g_yinit[(((size_t)b<<11)+e+1)*CH + c];
    size_t tok0 = (size_t)b*SS + c*CLEN;
    const __nv_bfloat162* up = (const __nv_bfloat162*)g_cu + ((tok0*EE + e) >> 1);
    const __nv_bfloat162* gp = (const __nv_bfloat162*)g_xpg + ((tok0*(2*EE) + EE + e) >> 1);
    __nv_bfloat162* og = (__nv_bfloat162*)g_xg + ((tok0*EE + e) >> 1);
    #pragma unroll 4
    for (int t=0;t<CLEN;t++){
        float2 uv = __bfloat1622float2(up[(size_t)t*(EE/2)]);
        float2 gv = __bfloat1622float2(gp[(size_t)t*(2*EE/2)]);
        y0 = a0*y0 + uv.x;
        y1 = a1*y1 + uv.y;
        og[(size_t)t*(EE/2)] = __floats2bfloat162_rn(y0*sigf(gv.x), y1*sigf(gv.y));
    }
}

// ---------------- launch ----------------
extern "C" void kernel_launch(void* const* d_in, const int* in_sizes, int n_in,
                              void* d_out, int out_size){
    const float* x         = (const float*)d_in[0];
    const float* ln_g      = (const float*)d_in[1];
    const float* ln_b      = (const float*)d_in[2];
    const float* W_in      = (const float*)d_in[3];
    const float* b_in      = (const float*)d_in[4];
    const float* conv_w    = (const float*)d_in[5];
    const float* conv_b    = (const float*)d_in[6];
    const float* Amat      = (const float*)d_in[7];
    const float* Bmat      = (const float*)d_in[8];
    const float* W_c       = (const float*)d_in[9];
    const float* b_c       = (const float*)d_in[10];
    const float* W_d       = (const float*)d_in[11];
    const float* b_d       = (const float*)d_in[12];
    const float* log_delta = (const float*)d_in[13];
    const float* W_out     = (const float*)d_in[14];
    const float* b_out     = (const float*)d_in[15];
    float* out = (float*)d_out;

    cudaFuncSetAttribute(gemm_fp8<0>, cudaFuncAttributeMaxDynamicSharedMemorySize, FP8_SMEM);
    cudaFuncSetAttribute(gemm_fp8<1>, cudaFuncAttributeMaxDynamicSharedMemorySize, FP8_SMEM);
    cudaFuncSetAttribute(gemm_out, cudaFuncAttributeMaxDynamicSharedMemorySize, BF16_SMEM);

    wconv_kernel<<<4096, 256>>>(W_in, W_c, W_d, W_out);
    pre_small<<<8, 256>>>(log_delta, Amat, Bmat, b_c, b_d);
    ln_kernel<<<MM, 256>>>(x, ln_g, ln_b);
    gemm_fp8<0><<<dim3(32,32), 512, FP8_SMEM>>>(b_in);
    conv_kernel<<<256, 256>>>(conv_w, conv_b);
    gemm_fp8<1><<<dim3(32,32), 512, FP8_SMEM>>>(nullptr);
    scanA_kernel<<<256, 256>>>();
    scanB_kernel<<<32, 256>>>();
    scanC_kernel<<<256, 256>>>();
    gemm_out<<<dim3(8,32), 512, BF16_SMEM>>>(b_out, x, out);
}

// round 13
// speedup vs baseline: 1.4123x; 1.0949x over previous
#include <cuda_runtime.h>
#include <cuda_bf16.h>
#include <cuda_fp8.h>
#include <cstdint>

// Problem dims
#define BB 4
#define SS 2048
#define DD 1024
#define EE 2048
#define NN 16
#define MM (BB*SS)          // 8192 tokens
#define CH 32               // scan chunks per sequence
#define CLEN (SS/CH)        // 64

// ---------------- scratch (device globals; no allocation allowed) ----------
__device__ __align__(256) uint8_t g_xln8[(size_t)MM*DD];         // fp8 ln out
__device__ __align__(256) __nv_bfloat16 g_xpg[(size_t)MM*2*EE];  // x_proj (xp|gate) bf16
__device__ __align__(256) uint8_t g_xc8[(size_t)MM*EE];          // fp8 conv+silu out
__device__ __align__(256) __nv_bfloat16 g_cu [(size_t)MM*EE];    // cc*u (fused gemm1 epilogue)
__device__ __align__(256) __nv_bfloat16 g_xg [(size_t)MM*EE];    // gated ssm out bf16
__device__ __align__(256) uint8_t g_win8[(size_t)2*EE*DD];       // fp8 W_in
__device__ __align__(256) uint8_t g_wcd8[(size_t)2*EE*EE];       // fp8 interleaved W_c/W_d rows
__device__ __align__(256) __nv_bfloat16 g_wout[(size_t)DD*EE];   // bf16 W_out
__device__ float g_a[EE];
__device__ float g_cc[EE];
__device__ float g_biascat[2*EE];   // interleaved: [2f]=b_c[f], [2f+1]=b_d[f]
__device__ float g_ylast[BB*EE*CH];
__device__ float g_yinit[BB*EE*CH];

// ---------------- helpers ----------------
__device__ __forceinline__ uint32_t smem_u32(const void* p){
    return (uint32_t)__cvta_generic_to_shared(p);
}
__device__ __forceinline__ void cp_async16(uint32_t saddr, const void* gptr){
    asm volatile("cp.async.cg.shared.global [%0], [%1], 16;" :: "r"(saddr), "l"(gptr));
}
__device__ __forceinline__ void cp_commit(){ asm volatile("cp.async.commit_group;"); }
__device__ __forceinline__ void ldsm4(uint32_t& r0,uint32_t& r1,uint32_t& r2,uint32_t& r3,uint32_t addr){
    asm volatile("ldmatrix.sync.aligned.m8n8.x4.shared.b16 {%0,%1,%2,%3}, [%4];"
        : "=r"(r0),"=r"(r1),"=r"(r2),"=r"(r3) : "r"(addr));
}
__device__ __forceinline__ void mma_bf16(float* c, uint32_t a0,uint32_t a1,uint32_t a2,uint32_t a3,
                                         uint32_t b0,uint32_t b1){
    asm volatile("mma.sync.aligned.m16n8k16.row.col.f32.bf16.bf16.f32 "
        "{%0,%1,%2,%3},{%4,%5,%6,%7},{%8,%9},{%0,%1,%2,%3};"
        : "+f"(c[0]),"+f"(c[1]),"+f"(c[2]),"+f"(c[3])
        : "r"(a0),"r"(a1),"r"(a2),"r"(a3),"r"(b0),"r"(b1));
}
__device__ __forceinline__ void mma_fp8(float* c, uint32_t a0,uint32_t a1,uint32_t a2,uint32_t a3,
                                        uint32_t b0,uint32_t b1){
    asm volatile("mma.sync.aligned.m16n8k32.row.col.f32.e4m3.e4m3.f32 "
        "{%0,%1,%2,%3},{%4,%5,%6,%7},{%8,%9},{%0,%1,%2,%3};"
        : "+f"(c[0]),"+f"(c[1]),"+f"(c[2]),"+f"(c[3])
        : "r"(a0),"r"(a1),"r"(a2),"r"(a3),"r"(b0),"r"(b1));
}
__device__ __forceinline__ float sigf(float x){ return 1.f/(1.f+__expf(-x)); }
__device__ __forceinline__ uint32_t bf2u(__nv_bfloat162 v){
    uint32_t u; memcpy(&u, &v, 4); return u;
}
__device__ __forceinline__ uint16_t f2fp8x2(float a, float b){
    return (uint16_t)__nv_cvt_float2_to_fp8x2(make_float2(a,b), __NV_SATFINITE, __NV_E4M3);
}
__device__ __forceinline__ uint32_t f4fp8x4(float4 v){
    uint32_t lo = f2fp8x2(v.x, v.y);
    uint32_t hi = f2fp8x2(v.z, v.w);
    return lo | (hi << 16);
}

// ---------------- merged prep: ln (blocks 0..8191), weight conv (8192..12287),
//                  small precompute (12288..12295) ----------------
__global__ void prep_kernel(const float* __restrict__ win, const float* __restrict__ wc,
                            const float* __restrict__ wd, const float* __restrict__ wout,
                            const float* __restrict__ log_delta, const float* __restrict__ Amat,
                            const float* __restrict__ Bmat, const float* __restrict__ bc,
                            const float* __restrict__ bd, const float* __restrict__ x,
                            const float* __restrict__ g, const float* __restrict__ bta){
    int blk = blockIdx.x;
    int tid = threadIdx.x;
    if (blk < 8192){
        // ---- layernorm row -> fp8
        int m = blk;
        const float* row = x + (size_t)m*DD;
        float v[4], s=0.f, s2=0.f;
        #pragma unroll
        for (int i=0;i<4;i++){ v[i]=row[tid+i*256]; s+=v[i]; s2+=v[i]*v[i]; }
        #pragma unroll
        for (int o=16;o;o>>=1){ s += __shfl_xor_sync(~0u,s,o); s2 += __shfl_xor_sync(~0u,s2,o); }
        __shared__ float sh[2][8];
        int w = tid>>5, l = tid&31;
        if (l==0){ sh[0][w]=s; sh[1][w]=s2; }
        __syncthreads();
        s=0.f; s2=0.f;
        #pragma unroll
        for (int j=0;j<8;j++){ s+=sh[0][j]; s2+=sh[1][j]; }
        float mu = s*(1.f/DD);
        float var = s2*(1.f/DD) - mu*mu;
        float rs = rsqrtf(var + 1e-5f);
        #pragma unroll
        for (int i=0;i<4;i++){
            int c = tid+i*256;
            float val = (v[i]-mu)*rs*g[c] + bta[c];
            g_xln8[(size_t)m*DD + c] = (uint8_t)__nv_cvt_float_to_fp8(val, __NV_SATFINITE, __NV_E4M3);
        }
    } else if (blk < 12288){
        // ---- weight conversion (4 elems per thread)
        size_t idx = (size_t)(blk-8192)*256 + tid;   // [0, 1048576)
        size_t i4 = idx*4;
        *reinterpret_cast<uint32_t*>(&g_win8[i4]) = f4fp8x4(*reinterpret_cast<const float4*>(&win[i4]));
        {
            size_t f = i4 >> 11;
            size_t k = i4 & 2047;
            *reinterpret_cast<uint32_t*>(&g_wcd8[(2*f)*EE + k])   = f4fp8x4(*reinterpret_cast<const float4*>(&wc[i4]));
            *reinterpret_cast<uint32_t*>(&g_wcd8[(2*f+1)*EE + k]) = f4fp8x4(*reinterpret_cast<const float4*>(&wd[i4]));
        }
        if (i4 < (size_t)DD*EE){
            float4 v = *reinterpret_cast<const float4*>(&wout[i4]);
            uint2 r;
            r.x = bf2u(__floats2bfloat162_rn(v.x, v.y));
            r.y = bf2u(__floats2bfloat162_rn(v.z, v.w));
            *reinterpret_cast<uint2*>(&g_wout[i4]) = r;
        }
    } else {
        int e = (blk-12288)*256 + tid;
        if (e < EE){
            float dl = log_delta[e];
            float sp = (dl > 20.f) ? dl : log1pf(expf(dl));
            g_a[e] = expf(-sp);
            float s = 0.f;
            #pragma unroll
            for (int n=0; n<NN; n++) s += Amat[e*NN+n]*Bmat[e*NN+n];
            g_cc[e] = s;
            g_biascat[2*e]   = bc[e];
            g_biascat[2*e+1] = bd[e];
        }
    }
}

// ---------------- persistent FP8 GEMM -------------------------------------
// C[m,n] = sum_k A[m,k]*B[n,k]; BM=256 BN=128, 512 thr (4x4 warps, 64x32 warp
// tile), 64B K chunks, 4-stage cp.async pipeline, persistent tile stream,
// both k32-step fragments loaded up-front (double-buffered).
// MODE 0: A=g_xln8 (K=1024) B=g_win8 -> g_xpg bf16 (+b_in)
// MODE 1: A=g_xc8  (K=2048) B=g_wcd8 -> g_cu fused cc*(U+bc)*sig(V+bd)
#define SDB 80u
#define A_ST (256u*SDB)
#define B_ST (128u*SDB)
#define STT (A_ST + B_ST)
#define FP8_SMEM (4*STT)                // 122880
#define NSM 148

template<int MODE>
__global__ __launch_bounds__(512,1) void gemm_fp8(const float* __restrict__ bias_p){
    constexpr int K_ = (MODE==0)?1024:2048;
    constexpr int KT = K_/64;            // 16 or 32 (power of 2)
    constexpr int KTM = KT-1;
    constexpr int NTILES = 1024;         // 32 M-tiles x 32 N-tiles
    const uint8_t* A  = (MODE==0)? g_xln8 : g_xc8;
    const uint8_t* Bw = (MODE==0)? g_win8 : g_wcd8;

    extern __shared__ uint8_t smem[];
    const uint32_t sbase = smem_u32(smem);
    const int tid = threadIdx.x, lane = tid & 31, warp = tid >> 5;
    const int wm = warp >> 2, wn = warp & 3;
    const int bid = blockIdx.x;

    const int nmy = (NTILES - 1 - bid)/NSM + 1;
    const int qtot = nmy*KT;

    // per-thread loader constants
    const int al_row0 = tid >> 2, al_seg = (tid & 3) * 16;
    const uint32_t al_sm = (uint32_t)(al_row0*SDB + al_seg);
    const uint32_t bl_sm = al_sm;          // same formula, row<128
    // per-thread ldsm constants
    const uint32_t rA0 = (uint32_t)((wm*64 + (lane&15))*SDB + (lane>>4)*16);
    const uint32_t rB0 = (uint32_t)((wn*32 + ((lane>>4)<<3) + (lane&7))*SDB + ((lane>>3)&1)*16);

    auto load_chunk = [&](int q){
        if (q < qtot){
            int ti = q >> ((KT==16)?4:5);
            int kt = q & KTM;
            int t  = bid + ti*NSM;
            int bm = (t >> 5) * 256, bn = (t & 31) * 128;
            uint32_t a0 = sbase + (uint32_t)(q & 3)*STT;
            const uint8_t* gA = A  + (size_t)bm*K_ + kt*64;
            const uint8_t* gB = Bw + (size_t)bn*K_ + kt*64;
            cp_async16(a0 + al_sm,                 gA + (size_t)al_row0*K_ + al_seg);
            cp_async16(a0 + al_sm + 128u*SDB,      gA + (size_t)(al_row0+128)*K_ + al_seg);
            cp_async16(a0 + A_ST + bl_sm,          gB + (size_t)al_row0*K_ + al_seg);
        }
        cp_commit();
    };

    float acc[4][4][4];
    #pragma unroll
    for (int i=0;i<4;i++) for (int j=0;j<4;j++) for (int q=0;q<4;q++) acc[i][j][q]=0.f;

    load_chunk(0); load_chunk(1); load_chunk(2);

    for (int q=0; q<qtot; q++){
        asm volatile("cp.async.wait_group 2;" ::: "memory");
        __syncthreads();
        load_chunk(q+3);

        uint32_t baseA = sbase + (uint32_t)(q & 3)*STT;
        uint32_t baseB = baseA + A_ST;
        uint32_t afr[2][4][4], bfr[2][2][4];
        // issue ALL ldsm for both k32 steps up-front
        #pragma unroll
        for (int p=0;p<2;p++){
            int cb = p*32;
            #pragma unroll
            for (int i=0;i<4;i++){
                ldsm4(afr[p][i][0],afr[p][i][1],afr[p][i][2],afr[p][i][3],
                      baseA + rA0 + (uint32_t)(i*16)*SDB + cb);
            }
            #pragma unroll
            for (int jp=0;jp<2;jp++){
                ldsm4(bfr[p][jp][0],bfr[p][jp][1],bfr[p][jp][2],bfr[p][jp][3],
                      baseB + rB0 + (uint32_t)(jp*16)*SDB + cb);
            }
        }
        #pragma unroll
        for (int p=0;p<2;p++){
            #pragma unroll
            for (int i=0;i<4;i++){
                #pragma unroll
                for (int j=0;j<4;j++){
                    int jp=j>>1, o=(j&1)*2;
                    mma_fp8(acc[i][j], afr[p][i][0],afr[p][i][1],afr[p][i][2],afr[p][i][3],
                            bfr[p][jp][o], bfr[p][jp][o+1]);
                }
            }
        }

        if ((q & KTM) == KTM){
            // epilogue for tile t
            int ti = q >> ((KT==16)?4:5);
            int t  = bid + ti*NSM;
            int bm = (t >> 5) * 256, bn = (t & 31) * 128;
            const int ro = lane >> 2, co = (lane & 3) * 2;
            #pragma unroll
            for (int i=0;i<4;i++){
                #pragma unroll
                for (int j=0;j<4;j++){
                    int r  = bm + wm*64 + i*16 + ro;
                    int cc = bn + wn*32 + j*8 + co;
                    if (MODE == 0){
                        float b0 = bias_p[cc], b1 = bias_p[cc+1];
                        *reinterpret_cast<__nv_bfloat162*>(&g_xpg[(size_t)r*4096 + cc])
                            = __floats2bfloat162_rn(acc[i][j][0]+b0, acc[i][j][1]+b1);
                        *reinterpret_cast<__nv_bfloat162*>(&g_xpg[(size_t)(r+8)*4096 + cc])
                            = __floats2bfloat162_rn(acc[i][j][2]+b0, acc[i][j][3]+b1);
                    } else {
                        float b0 = g_biascat[cc], b1 = g_biascat[cc+1];
                        int f = cc >> 1;
                        float cf = g_cc[f];
                        float u0 = cf * (acc[i][j][0]+b0) * sigf(acc[i][j][1]+b1);
                        float u1 = cf * (acc[i][j][2]+b0) * sigf(acc[i][j][3]+b1);
                        g_cu[(size_t)r*EE + f]     = __float2bfloat16(u0);
                        g_cu[(size_t)(r+8)*EE + f] = __float2bfloat16(u1);
                    }
                    acc[i][j][0]=0.f; acc[i][j][1]=0.f; acc[i][j][2]=0.f; acc[i][j][3]=0.f;
                }
            }
        }
    }
}

// ---------------- bf16 GEMM (out): out = xg @ W_out^T + b + resid ----------
#define SD 72u
#define A_STAGE_B (256u*SD*2u)
#define B_STAGE_B (128u*SD*2u)
#define STAGE_TOT (A_STAGE_B + B_STAGE_B)
#define BF16_SMEM (3*STAGE_TOT)          // 165888

__global__ __launch_bounds__(512,1) void gemm_out(const float* __restrict__ bias_p,
                                                  const float* __restrict__ resid,
                                                  float* __restrict__ outf){
    constexpr int N_ = 1024;
    constexpr int K_ = 2048;
    constexpr int KT = K_/64;
    const __nv_bfloat16* A  = g_xg;
    const __nv_bfloat16* Bw = g_wout;

    extern __shared__ uint8_t smemb[];
    const uint32_t sbase = smem_u32(smemb);

    const int tid = threadIdx.x;
    const int lane = tid & 31, warp = tid >> 5;
    const int wm = warp >> 2, wn = warp & 3;
    const int bm = blockIdx.y * 256, bn = blockIdx.x * 128;

    float acc[4][4][4];
    #pragma unroll
    for (int i=0;i<4;i++) for (int j=0;j<4;j++) for (int q=0;q<4;q++) acc[i][j][q]=0.f;

    auto load_tile = [&](int kt, int s){
        uint32_t a0 = sbase + (uint32_t)s*STAGE_TOT;
        uint32_t b0 = a0 + A_STAGE_B;
        #pragma unroll
        for (int h=0; h<4; h++){
            int c = tid + h*512;
            int row = c >> 3, seg = (c & 7) * 8;
            cp_async16(a0 + (uint32_t)((row*SD + seg)*2),
                       A + (size_t)(bm+row)*K_ + kt*64 + seg);
        }
        #pragma unroll
        for (int h=0; h<2; h++){
            int c = tid + h*512;
            int row = c >> 3, seg = (c & 7) * 8;
            cp_async16(b0 + (uint32_t)((row*SD + seg)*2),
                       Bw + (size_t)(bn+row)*K_ + kt*64 + seg);
        }
        cp_commit();
    };

    const int la_row = lane & 15;
    const int la_c8  = (lane >> 4) << 3;
    const int lb_row = ((lane >> 4) << 3) + (lane & 7);
    const int lb_c8  = ((lane >> 3) & 1) << 3;

    load_tile(0,0); load_tile(1,1);

    for (int kt=0; kt<KT; kt++){
        if (KT-1-kt >= 1) { asm volatile("cp.async.wait_group 1;" ::: "memory"); }
        else              { asm volatile("cp.async.wait_group 0;" ::: "memory"); }
        __syncthreads();
        if (kt+2 < KT) load_tile(kt+2, (kt+2)%3);

        uint32_t baseA = sbase + (uint32_t)(kt%3)*STAGE_TOT;
        uint32_t baseB = baseA + A_STAGE_B;
        #pragma unroll
        for (int k16=0;k16<4;k16++){
            int kb = k16*16;
            uint32_t a[4][4], bfr[2][4];
            #pragma unroll
            for (int i=0;i<4;i++){
                uint32_t ad = baseA + (uint32_t)(((wm*64 + i*16 + la_row)*SD + kb + la_c8)*2);
                ldsm4(a[i][0],a[i][1],a[i][2],a[i][3], ad);
            }
            #pragma unroll
            for (int jp=0;jp<2;jp++){
                uint32_t bd = baseB + (uint32_t)(((wn*32 + jp*16 + lb_row)*SD + kb + lb_c8)*2);
                ldsm4(bfr[jp][0],bfr[jp][1],bfr[jp][2],bfr[jp][3], bd);
            }
            #pragma unroll
            for (int i=0;i<4;i++){
                #pragma unroll
                for (int j=0;j<4;j++){
                    int jp=j>>1, o=(j&1)*2;
                    mma_bf16(acc[i][j], a[i][0],a[i][1],a[i][2],a[i][3], bfr[jp][o], bfr[jp][o+1]);
                }
            }
        }
    }

    const int ro = lane >> 2, co = (lane & 3) * 2;
    #pragma unroll
    for (int i=0;i<4;i++){
        #pragma unroll
        for (int j=0;j<4;j++){
            int r  = bm + wm*64 + i*16 + ro;
            int cc = bn + wn*32 + j*8 + co;
            float b0 = bias_p[cc], b1 = bias_p[cc+1];
            size_t o0 = (size_t)r*N_ + cc;
            size_t o1 = (size_t)(r+8)*N_ + cc;
            outf[o0]   = acc[i][j][0]+b0 + resid[o0];
            outf[o0+1] = acc[i][j][1]+b1 + resid[o0+1];
            outf[o1]   = acc[i][j][2]+b0 + resid[o1];
            outf[o1+1] = acc[i][j][3]+b1 + resid[o1+1];
        }
    }
}

// ---------------- causal depthwise conv K=4 + silu -> fp8 ----------------
__global__ void conv_kernel(const float* __restrict__ cw, const float* __restrict__ cb){
    int id = blockIdx.x*blockDim.x + threadIdx.x;     // 65536
    int ep = id & 1023;
    int c  = (id >> 10) & 15;
    int b  = id >> 14;
    int e  = ep*2;
    float w[4][2];
    #pragma unroll
    for (int k=0;k<4;k++){ w[k][0]=cw[e*4+k]; w[k][1]=cw[(e+1)*4+k]; }
    float bi0 = cb[e], bi1 = cb[e+1];
    const __nv_bfloat162* XP = reinterpret_cast<const __nv_bfloat162*>(g_xpg);
    uint16_t* XC = reinterpret_cast<uint16_t*>(g_xc8);
    int s0 = c*128;
    float2 win[3];
    #pragma unroll
    for (int k=0;k<3;k++){
        int s = s0 - 3 + k;
        if (s >= 0){
            __nv_bfloat162 t = XP[((size_t)(b*SS+s)*(2*EE) + e) >> 1];
            win[k] = make_float2(__low2float(t), __high2float(t));
        } else win[k] = make_float2(0.f, 0.f);
    }
    #pragma unroll 4
    for (int s=s0; s<s0+128; s++){
        __nv_bfloat162 t = XP[((size_t)(b*SS+s)*(2*EE) + e) >> 1];
        float2 cur = make_float2(__low2float(t), __high2float(t));
        float ax = bi0 + w[0][0]*win[0].x + w[1][0]*win[1].x + w[2][0]*win[2].x + w[3][0]*cur.x;
        float ay = bi1 + w[0][1]*win[0].y + w[1][1]*win[1].y + w[2][1]*win[2].y + w[3][1]*cur.y;
        ax = ax * sigf(ax);
        ay = ay * sigf(ay);
        XC[((size_t)(b*SS+s)*EE + e) >> 1] = f2fp8x2(ax, ay);
        win[0]=win[1]; win[1]=win[2]; win[2]=cur;
    }
}

// ---------------- chunked linear scan (CH=32 chunks of 64) ----------------
__global__ void scanA_kernel(){
    int id = blockIdx.x*blockDim.x + threadIdx.x;   // 131072
    int ep = id & 1023, c = (id >> 10) & (CH-1), b = id >> 15;
    int e = ep*2;
    float a0 = g_a[e], a1 = g_a[e+1];
    float y0 = 0.f, y1 = 0.f;
    size_t tok0 = (size_t)b*SS + c*CLEN;
    const __nv_bfloat162* Up = (const __nv_bfloat162*)g_cu + ((tok0*EE + e) >> 1);
    #pragma unroll 4
    for (int t=0;t<CLEN;t++){
        float2 uv = __bfloat1622float2(Up[(size_t)t*(EE/2)]);
        y0 = a0*y0 + uv.x;
        y1 = a1*y1 + uv.y;
    }
    g_ylast[(((size_t)b<<11)+e)*CH + c]   = y0;
    g_ylast[(((size_t)b<<11)+e+1)*CH + c] = y1;
}
__global__ void scanB_kernel(){
    int id = blockIdx.x*blockDim.x + threadIdx.x;   // 8192
    int e = id & 2047;
    float a = g_a[e];
    float aL = a;
    #pragma unroll
    for (int i=0;i<6;i++) aL *= aL;  // a^64
    float y = 0.f;
    #pragma unroll
    for (int c=0;c<CH;c++){
        g_yinit[id*CH + c] = y;
        y = g_ylast[id*CH + c] + aL*y;
    }
}
__global__ void scanC_kernel(){
    int id = blockIdx.x*blockDim.x + threadIdx.x;   // 131072
    int ep = id & 1023, c = (id >> 10) & (CH-1), b = id >> 15;
    int e = ep*2;
    float a0 = g_a[e], a1 = g_a[e+1];
    float y0 = g_yinit[(((size_t)b<<11)+e)*CH + c];
    float y1 = g_yinit[(((size_t)b<<11)+e+1)*CH + c];
    size_t tok0 = (size_t)b*SS + c*CLEN;
    const __nv_bfloat162* up = (const __nv_bfloat162*)g_cu + ((tok0*EE + e) >> 1);
    const __nv_bfloat162* gp = (const __nv_bfloat162*)g_xpg + ((tok0*(2*EE) + EE + e) >> 1);
    __nv_bfloat162* og = (__nv_bfloat162*)g_xg + ((tok0*EE + e) >> 1);
    #pragma unroll 4
    for (int t=0;t<CLEN;t++){
        float2 uv = __bfloat1622float2(up[(size_t)t*(EE/2)]);
        float2 gv = __bfloat1622float2(gp[(size_t)t*(2*EE/2)]);
        y0 = a0*y0 + uv.x;
        y1 = a1*y1 + uv.y;
        og[(size_t)t*(EE/2)] = __floats2bfloat162_rn(y0*sigf(gv.x), y1*sigf(gv.y));
    }
}

// ---------------- launch ----------------
extern "C" void kernel_launch(void* const* d_in, const int* in_sizes, int n_in,
                              void* d_out, int out_size){
    const float* x         = (const float*)d_in[0];
    const float* ln_g      = (const float*)d_in[1];
    const float* ln_b      = (const float*)d_in[2];
    const float* W_in      = (const float*)d_in[3];
    const float* b_in      = (const float*)d_in[4];
    const float* conv_w    = (const float*)d_in[5];
    const float* conv_b    = (const float*)d_in[6];
    const float* Amat      = (const float*)d_in[7];
    const float* Bmat      = (const float*)d_in[8];
    const float* W_c       = (const float*)d_in[9];
    const float* b_c       = (const float*)d_in[10];
    const float* W_d       = (const float*)d_in[11];
    const float* b_d       = (const float*)d_in[12];
    const float* log_delta = (const float*)d_in[13];
    const float* W_out     = (const float*)d_in[14];
    const float* b_out     = (const float*)d_in[15];
    float* out = (float*)d_out;

    cudaFuncSetAttribute(gemm_fp8<0>, cudaFuncAttributeMaxDynamicSharedMemorySize, FP8_SMEM);
    cudaFuncSetAttribute(gemm_fp8<1>, cudaFuncAttributeMaxDynamicSharedMemorySize, FP8_SMEM);
    cudaFuncSetAttribute(gemm_out, cudaFuncAttributeMaxDynamicSharedMemorySize, BF16_SMEM);

    prep_kernel<<<12296, 256>>>(W_in, W_c, W_d, W_out, log_delta, Amat, Bmat,
                                b_c, b_d, x, ln_g, ln_b);
    gemm_fp8<0><<<NSM, 512, FP8_SMEM>>>(b_in);
    conv_kernel<<<256, 256>>>(conv_w, conv_b);
    gemm_fp8<1><<<NSM, 512, FP8_SMEM>>>(nullptr);
    scanA_kernel<<<512, 256>>>();
    scanB_kernel<<<32, 256>>>();
    scanC_kernel<<<512, 256>>>();
    gemm_out<<<dim3(8,32), 512, BF16_SMEM>>>(b_out, x, out);
}